// round 3
// baseline (speedup 1.0000x reference)
#include <cuda_runtime.h>
#include <math.h>
#include <stdint.h>

#define S_LEN 2048
#define BATCH 2
#define HID   2048
#define NH    16
#define HD    128
#define M_ROWS (S_LEN * BATCH)   // 4096
#define N3H    (3 * HID)         // 6144

// Scratch (allocation-free: __device__ globals)
__device__ float g_q[BATCH * NH * S_LEN * HD];
__device__ float g_k[BATCH * NH * S_LEN * HD];
__device__ float g_v[BATCH * NH * S_LEN * HD];
__device__ float g_ctx[M_ROWS * HID];

// ---------------------------------------------------------------------------
// TF32 helpers
// ---------------------------------------------------------------------------
__device__ __forceinline__ float f2tf32(float x) {
    uint32_t u;
    asm("cvt.rna.tf32.f32 %0, %1;" : "=r"(u) : "f"(x));
    return __uint_as_float(u);
}

__device__ __forceinline__ void mma_tf32(float c[4],
                                         float a0, float a1, float a2, float a3,
                                         float b0, float b1) {
    asm volatile(
        "mma.sync.aligned.m16n8k8.row.col.f32.tf32.tf32.f32 "
        "{%0,%1,%2,%3}, {%4,%5,%6,%7}, {%8,%9}, {%0,%1,%2,%3};"
        : "+f"(c[0]), "+f"(c[1]), "+f"(c[2]), "+f"(c[3])
        : "r"(__float_as_uint(a0)), "r"(__float_as_uint(a1)),
          "r"(__float_as_uint(a2)), "r"(__float_as_uint(a3)),
          "r"(__float_as_uint(b0)), "r"(__float_as_uint(b1)));
}

// ---------------------------------------------------------------------------
// TF32x3 GEMM: out[M_ROWS, NDIM] = A[M_ROWS, HID] @ B[HID, NDIM]
// 128x128 block tile, BK=16, 256 threads (8 warps, 2x4), 64x32 warp tile.
// IS_QKV: A = hidden (arg), epilogue adds bias and scatters into g_q/g_k/g_v.
// !IS_QKV: A = g_ctx (device symbol, resolved in DEVICE code), plain store.
// ---------------------------------------------------------------------------
#define SMSTR 136   // padded smem row stride (floats)

template<int NDIM, bool IS_QKV>
__global__ __launch_bounds__(256) void gemm_tf32x3_kernel(
    const float* __restrict__ A, const float* __restrict__ B,
    const float* __restrict__ bias, float* __restrict__ out)
{
    __shared__ float sA[16 * SMSTR];   // sA[k][m]
    __shared__ float sB[16 * SMSTR];   // sB[k][n]

    const int tid  = threadIdx.x;
    const int lane = tid & 31;
    const int wid  = tid >> 5;
    const int wRow = wid >> 2;    // 0..1
    const int wCol = wid & 3;     // 0..3
    const int rowBase = blockIdx.y * 128;
    const int colBase = blockIdx.x * 128;

    const int lq = lane >> 2;     // groupID 0..7
    const int lr = lane & 3;      // threadID-in-group 0..3

    float c[4][4][4];
#pragma unroll
    for (int i = 0; i < 4; i++)
#pragma unroll
        for (int j = 0; j < 4; j++)
#pragma unroll
            for (int e = 0; e < 4; e++) c[i][j][e] = 0.0f;

    const int aF0 = tid * 2;
    const int aRow0 = aF0 >> 2,  aC0 = (aF0 & 3) * 4;
    const int aRow1 = (aF0 + 1) >> 2, aC1 = ((aF0 + 1) & 3) * 4;
    const int bRow0 = aF0 >> 5,  bC0 = (aF0 & 31) * 4;
    const int bRow1 = (aF0 + 1) >> 5, bC1 = ((aF0 + 1) & 31) * 4;

    // FIX vs R2: device-global A resolved in device code, never via host arg.
    const float* Asrc = IS_QKV ? A : (const float*)g_ctx;
    const float* Abase = Asrc + (size_t)rowBase * HID;
    const float* Bbase = B + colBase;

    float4 pa0, pa1, pb0, pb1;
    pa0 = *(const float4*)(Abase + (size_t)aRow0 * HID + aC0);
    pa1 = *(const float4*)(Abase + (size_t)aRow1 * HID + aC1);
    pb0 = *(const float4*)(Bbase + (size_t)bRow0 * NDIM + bC0);
    pb1 = *(const float4*)(Bbase + (size_t)bRow1 * NDIM + bC1);

    const int NIT = HID / 16;   // 128
    for (int it = 0; it < NIT; ++it) {
        sA[(aC0 + 0) * SMSTR + aRow0] = pa0.x;
        sA[(aC0 + 1) * SMSTR + aRow0] = pa0.y;
        sA[(aC0 + 2) * SMSTR + aRow0] = pa0.z;
        sA[(aC0 + 3) * SMSTR + aRow0] = pa0.w;
        sA[(aC1 + 0) * SMSTR + aRow1] = pa1.x;
        sA[(aC1 + 1) * SMSTR + aRow1] = pa1.y;
        sA[(aC1 + 2) * SMSTR + aRow1] = pa1.z;
        sA[(aC1 + 3) * SMSTR + aRow1] = pa1.w;
        *(float4*)&sB[bRow0 * SMSTR + bC0] = pb0;
        *(float4*)&sB[bRow1 * SMSTR + bC1] = pb1;
        __syncthreads();

        if (it + 1 < NIT) {
            const int k0 = (it + 1) * 16;
            pa0 = *(const float4*)(Abase + (size_t)aRow0 * HID + k0 + aC0);
            pa1 = *(const float4*)(Abase + (size_t)aRow1 * HID + k0 + aC1);
            pb0 = *(const float4*)(Bbase + (size_t)(k0 + bRow0) * NDIM + bC0);
            pb1 = *(const float4*)(Bbase + (size_t)(k0 + bRow1) * NDIM + bC1);
        }

#pragma unroll
        for (int ka = 0; ka < 16; ka += 8) {
            float ah[4][4], al[4][4];
#pragma unroll
            for (int i = 0; i < 4; i++) {
                const int r = wRow * 64 + i * 16 + lq;
                const int cA = ka + lr;
                const float x0 = sA[cA * SMSTR + r];
                const float x1 = sA[cA * SMSTR + r + 8];
                const float x2 = sA[(cA + 4) * SMSTR + r];
                const float x3 = sA[(cA + 4) * SMSTR + r + 8];
                ah[i][0] = f2tf32(x0); al[i][0] = f2tf32(x0 - ah[i][0]);
                ah[i][1] = f2tf32(x1); al[i][1] = f2tf32(x1 - ah[i][1]);
                ah[i][2] = f2tf32(x2); al[i][2] = f2tf32(x2 - ah[i][2]);
                ah[i][3] = f2tf32(x3); al[i][3] = f2tf32(x3 - ah[i][3]);
            }
            float bh[4][2], bl[4][2];
#pragma unroll
            for (int j = 0; j < 4; j++) {
                const int n = wCol * 32 + j * 8 + lq;
                const int kB = ka + lr;
                const float y0 = sB[kB * SMSTR + n];
                const float y1 = sB[(kB + 4) * SMSTR + n];
                bh[j][0] = f2tf32(y0); bl[j][0] = f2tf32(y0 - bh[j][0]);
                bh[j][1] = f2tf32(y1); bl[j][1] = f2tf32(y1 - bh[j][1]);
            }
#pragma unroll
            for (int i = 0; i < 4; i++)
#pragma unroll
                for (int j = 0; j < 4; j++) {
                    mma_tf32(c[i][j], ah[i][0], ah[i][1], ah[i][2], ah[i][3],
                             bh[j][0], bh[j][1]);
                    mma_tf32(c[i][j], ah[i][0], ah[i][1], ah[i][2], ah[i][3],
                             bl[j][0], bl[j][1]);
                    mma_tf32(c[i][j], al[i][0], al[i][1], al[i][2], al[i][3],
                             bh[j][0], bh[j][1]);
                }
        }
        __syncthreads();
    }

#pragma unroll
    for (int i = 0; i < 4; i++) {
        const int r0 = rowBase + wRow * 64 + i * 16 + lq;
#pragma unroll
        for (int j = 0; j < 4; j++) {
            const int cc = colBase + wCol * 32 + j * 8 + 2 * lr;
            if (IS_QKV) {
#pragma unroll
                for (int e = 0; e < 4; e++) {
                    const int r = r0 + (e >> 1) * 8;
                    const int col = cc + (e & 1);
                    const float v = c[i][j][e] + bias[col];
                    const int s = r >> 1;      // BATCH == 2
                    const int b = r & 1;
                    const int h = col / 384;
                    const int jj = col - h * 384;
                    const int which = jj >> 7;   // 0=q, 1=k, 2=v
                    const int dd = jj & 127;
                    float* dst = (which == 0) ? g_q : (which == 1 ? g_k : g_v);
                    dst[(size_t)(((b * NH + h) * S_LEN) + s) * HD + dd] = v;
                }
            } else {
                float2 v0 = make_float2(c[i][j][0], c[i][j][1]);
                float2 v1 = make_float2(c[i][j][2], c[i][j][3]);
                *(float2*)(out + (size_t)r0 * NDIM + cc) = v0;
                *(float2*)(out + (size_t)(r0 + 8) * NDIM + cc) = v1;
            }
        }
    }
}

// ---------------------------------------------------------------------------
// Flash attention: one block = (b, h, 64-query tile). Online softmax.
// ---------------------------------------------------------------------------
#define BQ 64
#define BKT 64
#define QSTR 132
#define PSTR 68
#define NQT (S_LEN / BQ)  // 32
#define ATTN_SMEM ((BQ * QSTR * 3 + BQ * PSTR) * 4)  // 118784 bytes

__global__ __launch_bounds__(256) void attn_kernel(
    const unsigned char* __restrict__ mask)
{
    extern __shared__ float sm[];
    float* sQ = sm;
    float* sK = sQ + BQ * QSTR;
    float* sV = sK + BKT * QSTR;
    float* sP = sV + BKT * QSTR;

    const int bid = blockIdx.x;
    const int qt = NQT - 1 - (bid % NQT);
    const int bh = bid / NQT;
    const int b = bh / NH;
    const int h = bh % NH;
    const int q0 = qt * BQ;

    const int tid = threadIdx.x;
    const int ty = tid >> 4, tx = tid & 15;
    const float inv_norm = 0.08838834764831845f;

    {
        const float* Qg = g_q + ((size_t)bh * S_LEN + q0) * HD;
#pragma unroll
        for (int it = 0; it < 8; ++it) {
            int e = tid + it * 256;
            int row = e >> 5;
            int c4 = (e & 31) * 4;
            *(float4*)&sQ[row * QSTR + c4] = *(const float4*)&Qg[row * HD + c4];
        }
    }

    float m_i[4], l_i[4], o[4][8];
#pragma unroll
    for (int ii = 0; ii < 4; ii++) {
        m_i[ii] = -1e30f; l_i[ii] = 0.0f;
#pragma unroll
        for (int cc = 0; cc < 8; cc++) o[ii][cc] = 0.0f;
    }

    for (int kt = 0; kt <= qt; ++kt) {
        const int k0 = kt * BKT;
        __syncthreads();
        {
            const float* Kg = g_k + ((size_t)bh * S_LEN + k0) * HD;
            const float* Vg = g_v + ((size_t)bh * S_LEN + k0) * HD;
#pragma unroll
            for (int it = 0; it < 8; ++it) {
                int e = tid + it * 256;
                int row = e >> 5;
                int c4 = (e & 31) * 4;
                *(float4*)&sK[row * QSTR + c4] = *(const float4*)&Kg[row * HD + c4];
                *(float4*)&sV[row * QSTR + c4] = *(const float4*)&Vg[row * HD + c4];
            }
        }
        __syncthreads();

        float acc[4][4];
#pragma unroll
        for (int ii = 0; ii < 4; ii++)
#pragma unroll
            for (int jj = 0; jj < 4; jj++) acc[ii][jj] = 0.0f;

        const float4* q4 = (const float4*)sQ;
        const float4* k4 = (const float4*)sK;
#pragma unroll 8
        for (int d4 = 0; d4 < 32; ++d4) {
            float4 qv[4], kv[4];
#pragma unroll
            for (int ii = 0; ii < 4; ii++) qv[ii] = q4[(ty * 4 + ii) * 33 + d4];
#pragma unroll
            for (int jj = 0; jj < 4; jj++) kv[jj] = k4[(tx * 4 + jj) * 33 + d4];
#pragma unroll
            for (int ii = 0; ii < 4; ii++)
#pragma unroll
                for (int jj = 0; jj < 4; jj++) {
                    acc[ii][jj] = fmaf(qv[ii].x, kv[jj].x, acc[ii][jj]);
                    acc[ii][jj] = fmaf(qv[ii].y, kv[jj].y, acc[ii][jj]);
                    acc[ii][jj] = fmaf(qv[ii].z, kv[jj].z, acc[ii][jj]);
                    acc[ii][jj] = fmaf(qv[ii].w, kv[jj].w, acc[ii][jj]);
                }
        }

#pragma unroll
        for (int ii = 0; ii < 4; ii++) {
            const int sg = q0 + ty * 4 + ii;
            const unsigned char* mrow = mask + ((size_t)b * S_LEN + sg) * S_LEN + k0;
            float vmax = -1e30f;
#pragma unroll
            for (int jj = 0; jj < 4; jj++) {
                const int tl = tx * 4 + jj;
                const int tg = k0 + tl;
                const bool masked = (tg > sg) || (mrow[tl] != 0);
                const float sval = masked ? -10000.0f : acc[ii][jj] * inv_norm;
                acc[ii][jj] = sval;
                vmax = fmaxf(vmax, sval);
            }
#pragma unroll
            for (int off = 8; off >= 1; off >>= 1)
                vmax = fmaxf(vmax, __shfl_xor_sync(0xffffffffu, vmax, off, 16));
            const float m_new = fmaxf(m_i[ii], vmax);
            const float corr = __expf(m_i[ii] - m_new);
            float lsum = 0.0f;
#pragma unroll
            for (int jj = 0; jj < 4; jj++) {
                const float p = __expf(acc[ii][jj] - m_new);
                lsum += p;
                sP[(ty * 4 + ii) * PSTR + tx * 4 + jj] = p;
            }
#pragma unroll
            for (int off = 8; off >= 1; off >>= 1)
                lsum += __shfl_xor_sync(0xffffffffu, lsum, off, 16);
            l_i[ii] = l_i[ii] * corr + lsum;
            m_i[ii] = m_new;
#pragma unroll
            for (int cc = 0; cc < 8; cc++) o[ii][cc] *= corr;
        }
        __syncthreads();

        const float4* v4 = (const float4*)sV;
#pragma unroll 4
        for (int j = 0; j < BKT; ++j) {
            const float4 va = v4[j * 33 + tx * 2];
            const float4 vb = v4[j * 33 + tx * 2 + 1];
#pragma unroll
            for (int ii = 0; ii < 4; ii++) {
                const float p = sP[(ty * 4 + ii) * PSTR + j];
                o[ii][0] = fmaf(p, va.x, o[ii][0]);
                o[ii][1] = fmaf(p, va.y, o[ii][1]);
                o[ii][2] = fmaf(p, va.z, o[ii][2]);
                o[ii][3] = fmaf(p, va.w, o[ii][3]);
                o[ii][4] = fmaf(p, vb.x, o[ii][4]);
                o[ii][5] = fmaf(p, vb.y, o[ii][5]);
                o[ii][6] = fmaf(p, vb.z, o[ii][6]);
                o[ii][7] = fmaf(p, vb.w, o[ii][7]);
            }
        }
    }

#pragma unroll
    for (int ii = 0; ii < 4; ii++) {
        const int sg = q0 + ty * 4 + ii;
        const float inv_l = 1.0f / l_i[ii];
        float* dst = g_ctx + ((size_t)sg * BATCH + b) * HID + h * HD + tx * 8;
        float4 r0, r1;
        r0.x = o[ii][0] * inv_l; r0.y = o[ii][1] * inv_l;
        r0.z = o[ii][2] * inv_l; r0.w = o[ii][3] * inv_l;
        r1.x = o[ii][4] * inv_l; r1.y = o[ii][5] * inv_l;
        r1.z = o[ii][6] * inv_l; r1.w = o[ii][7] * inv_l;
        *(float4*)dst = r0;
        *(float4*)(dst + 4) = r1;
    }
}

__global__ void copy_bias_kernel(const float* __restrict__ bias, float* __restrict__ dst)
{
    int i = blockIdx.x * blockDim.x + threadIdx.x;
    if (i < HID) dst[i] = bias[i];
}

// ---------------------------------------------------------------------------
extern "C" void kernel_launch(void* const* d_in, const int* in_sizes, int n_in,
                              void* d_out, int out_size)
{
    const float* hidden   = (const float*)d_in[0];
    const unsigned char* mask = (const unsigned char*)d_in[1];
    const float* qkv_w    = (const float*)d_in[2];
    const float* qkv_b    = (const float*)d_in[3];
    const float* proj_w   = (const float*)d_in[4];
    const float* proj_b   = (const float*)d_in[5];
    float* out = (float*)d_out;

    cudaFuncSetAttribute(attn_kernel,
                         cudaFuncAttributeMaxDynamicSharedMemorySize, ATTN_SMEM);

    dim3 qkvGrid(N3H / 128, M_ROWS / 128);   // 48 x 32
    gemm_tf32x3_kernel<N3H, true><<<qkvGrid, 256>>>(hidden, qkv_w, qkv_b, nullptr);

    attn_kernel<<<BATCH * NH * NQT, 256, ATTN_SMEM>>>(mask);

    dim3 projGrid(HID / 128, M_ROWS / 128);  // 16 x 32
    gemm_tf32x3_kernel<HID, false><<<projGrid, 256>>>(nullptr, proj_w, nullptr, out);

    if (out_size > M_ROWS * HID) {
        copy_bias_kernel<<<(HID + 255) / 256, 256>>>(proj_b, out + (size_t)M_ROWS * HID);
    }
}

// round 6
// speedup vs baseline: 2.0104x; 2.0104x over previous
#include <cuda_runtime.h>
#include <cuda_bf16.h>
#include <math.h>
#include <stdint.h>

#define S_LEN 2048
#define BATCH 2
#define HID   2048
#define NH    16
#define HD    128
#define M_ROWS (S_LEN * BATCH)   // 4096
#define N3H    (3 * HID)         // 6144

// ---------------------------------------------------------------------------
// Device-global scratch (allocation-free)
// ---------------------------------------------------------------------------
__device__ float g_q[BATCH * NH * S_LEN * HD];
__device__ float g_k[BATCH * NH * S_LEN * HD];
__device__ float g_v[BATCH * NH * S_LEN * HD];
__device__ float g_ctx[M_ROWS * HID];

__device__ __nv_bfloat16 g_ahi[M_ROWS * HID];       // hidden split
__device__ __nv_bfloat16 g_alo[M_ROWS * HID];
__device__ __nv_bfloat16 g_chi[M_ROWS * HID];       // ctx split
__device__ __nv_bfloat16 g_clo[M_ROWS * HID];
__device__ __nv_bfloat16 g_wqh[(size_t)N3H * HID];  // qkv_w^T split [6144][2048]
__device__ __nv_bfloat16 g_wql[(size_t)N3H * HID];
__device__ __nv_bfloat16 g_wph[(size_t)HID * HID];  // proj_w^T split [2048][2048]
__device__ __nv_bfloat16 g_wpl[(size_t)HID * HID];

// ---------------------------------------------------------------------------
// MMA / ldmatrix helpers (sm_80-level PTX: compiles at sm_103 family target)
// ---------------------------------------------------------------------------
__device__ __forceinline__ uint32_t smem_u32(const void* p) {
    uint32_t a;
    asm("{ .reg .u64 t; cvta.to.shared.u64 t, %1; cvt.u32.u64 %0, t; }"
        : "=r"(a) : "l"(p));
    return a;
}

__device__ __forceinline__ void ldmx4(uint32_t r[4], uint32_t addr) {
    asm volatile("ldmatrix.sync.aligned.m8n8.x4.shared.b16 {%0,%1,%2,%3}, [%4];"
                 : "=r"(r[0]), "=r"(r[1]), "=r"(r[2]), "=r"(r[3]) : "r"(addr));
}

__device__ __forceinline__ void mma_bf16(float c[4],
                                         uint32_t a0, uint32_t a1, uint32_t a2, uint32_t a3,
                                         uint32_t b0, uint32_t b1) {
    asm volatile(
        "mma.sync.aligned.m16n8k16.row.col.f32.bf16.bf16.f32 "
        "{%0,%1,%2,%3}, {%4,%5,%6,%7}, {%8,%9}, {%0,%1,%2,%3};"
        : "+f"(c[0]), "+f"(c[1]), "+f"(c[2]), "+f"(c[3])
        : "r"(a0), "r"(a1), "r"(a2), "r"(a3), "r"(b0), "r"(b1));
}

// ---------------------------------------------------------------------------
// Split kernels: fp32 -> bf16 hi + bf16 lo
// ---------------------------------------------------------------------------
__global__ void split_hidden_kernel(const float* __restrict__ in)
{
    int i = blockIdx.x * blockDim.x + threadIdx.x;
    float x = in[i];
    __nv_bfloat16 h = __float2bfloat16(x);
    g_ahi[i] = h;
    g_alo[i] = __float2bfloat16(x - __bfloat162float(h));
}
__global__ void split_ctx_kernel()
{
    int i = blockIdx.x * blockDim.x + threadIdx.x;
    float x = g_ctx[i];
    __nv_bfloat16 h = __float2bfloat16(x);
    g_chi[i] = h;
    g_clo[i] = __float2bfloat16(x - __bfloat162float(h));
}

// Transpose + split: in [HID][NIN] fp32 -> out [NIN][HID] bf16 hi/lo
template<int NIN, int WSEL>
__global__ void transpose_split_kernel(const float* __restrict__ W)
{
    __shared__ float s[32][33];
    const int tx = threadIdx.x, ty = threadIdx.y;
    const int n0 = blockIdx.x * 32, k0 = blockIdx.y * 32;
    __nv_bfloat16* outHi = (WSEL == 0) ? g_wqh : g_wph;
    __nv_bfloat16* outLo = (WSEL == 0) ? g_wql : g_wpl;
#pragma unroll
    for (int i = 0; i < 4; i++) {
        int k = k0 + ty + i * 8;
        s[ty + i * 8][tx] = W[(size_t)k * NIN + n0 + tx];
    }
    __syncthreads();
#pragma unroll
    for (int i = 0; i < 4; i++) {
        int n = n0 + ty + i * 8;
        int k = k0 + tx;
        float x = s[tx][ty + i * 8];
        __nv_bfloat16 h = __float2bfloat16(x);
        outHi[(size_t)n * HID + k] = h;
        outLo[(size_t)n * HID + k] = __float2bfloat16(x - __bfloat162float(h));
    }
}

// ---------------------------------------------------------------------------
// bf16x3 HMMA GEMM: C[4096, NDIM] = A[4096, 2048] @ B[2048, NDIM]
// CTA tile 128x128, BK=32 bf16. 256 threads = 8 warps (2x4), 64x32 warp tile.
// A hi/lo row-major [m][k]; B^T hi/lo row-major [n][k]. Fragments via
// ldmatrix from XOR-swizzled smem (row stride 64B, unit' = unit ^ ((row>>1)&3)).
// SRC 0: A=hidden split, B=qkvW^T, epilogue bias + scatter q/k/v [b,h,s,d].
// SRC 1: A=ctx split,    B=projW^T, epilogue plain store.
// ---------------------------------------------------------------------------
#define TILE_BYTES 8192   // 128 rows x 32 bf16 x 2B
#define O_AH 0
#define O_AL 8192
#define O_BH 16384
#define O_BL 24576

__device__ __forceinline__ uint32_t swz_off(int row, int unit) {
    return (uint32_t)(row * 64 + ((unit ^ ((row >> 1) & 3)) << 4));
}

template<int NDIM, int SRC>
__global__ __launch_bounds__(256) void gemm_hmma_kernel(
    const float* __restrict__ bias, float* __restrict__ out)
{
    __shared__ char smem[4 * TILE_BYTES];
    const uint32_t sbase = smem_u32(smem);

    const int tid  = threadIdx.x;
    const int lane = tid & 31;
    const int wid  = tid >> 5;
    const int wRow = wid >> 2;    // 0..1 -> 64-row strip
    const int wCol = wid & 3;     // 0..3 -> 32-col strip
    const int rowBase = blockIdx.y * 128;
    const int colBase = blockIdx.x * 128;

    const __nv_bfloat16* Ahi = (SRC == 0) ? g_ahi : g_chi;
    const __nv_bfloat16* Alo = (SRC == 0) ? g_alo : g_clo;
    const __nv_bfloat16* Bhi = (SRC == 0) ? g_wqh : g_wph;
    const __nv_bfloat16* Blo = (SRC == 0) ? g_wql : g_wpl;

    float c[4][4][4];
#pragma unroll
    for (int i = 0; i < 4; i++)
#pragma unroll
        for (int j = 0; j < 4; j++)
#pragma unroll
            for (int e = 0; e < 4; e++) c[i][j][e] = 0.0f;

    // global->smem geometry: 512 16B-units per tile; thread handles units tid, tid+256
    int uRow[2], uUnit[2];
    uint32_t uSwz[2];
#pragma unroll
    for (int i = 0; i < 2; i++) {
        int u = tid + i * 256;
        uRow[i]  = u >> 2;
        uUnit[i] = u & 3;
        uSwz[i]  = swz_off(uRow[i], uUnit[i]);
    }

    // ldmatrix address components (per-lane constants)
    const int aRowLane  = lane & 15;
    const int aUnitSel  = lane >> 4;          // 0..1
    const int bRowLane  = (lane & 7) + ((lane >> 4) & 1) * 8;
    const int bUnitSel  = (lane >> 3) & 1;

    uint32_t aAddrBase[4], bAddrBase[2];      // swizzle-resolved per-block-row bases
    int aMask[4], bMask[2];
#pragma unroll
    for (int i = 0; i < 4; i++) {
        int r = wRow * 64 + i * 16 + aRowLane;
        aMask[i] = (r >> 1) & 3;
        aAddrBase[i] = (uint32_t)(r * 64);
    }
#pragma unroll
    for (int j2 = 0; j2 < 2; j2++) {
        int r = wCol * 32 + j2 * 16 + bRowLane;
        bMask[j2] = (r >> 1) & 3;
        bAddrBase[j2] = (uint32_t)(r * 64);
    }

    const int NIT = HID / 32;   // 64
    uint4 pAh[2], pAl[2], pBh[2], pBl[2];

    // preload iter 0
#pragma unroll
    for (int i = 0; i < 2; i++) {
        size_t aOff = (size_t)(rowBase + uRow[i]) * HID + uUnit[i] * 8;
        size_t bOff = (size_t)(colBase + uRow[i]) * HID + uUnit[i] * 8;
        pAh[i] = *(const uint4*)(Ahi + aOff);
        pAl[i] = *(const uint4*)(Alo + aOff);
        pBh[i] = *(const uint4*)(Bhi + bOff);
        pBl[i] = *(const uint4*)(Blo + bOff);
    }

    for (int it = 0; it < NIT; ++it) {
        // store staged tiles into swizzled smem
#pragma unroll
        for (int i = 0; i < 2; i++) {
            *(uint4*)(smem + O_AH + uSwz[i]) = pAh[i];
            *(uint4*)(smem + O_AL + uSwz[i]) = pAl[i];
            *(uint4*)(smem + O_BH + uSwz[i]) = pBh[i];
            *(uint4*)(smem + O_BL + uSwz[i]) = pBl[i];
        }
        __syncthreads();

        // prefetch next stage (overlaps with MMA)
        if (it + 1 < NIT) {
            const int k0 = (it + 1) * 32;
#pragma unroll
            for (int i = 0; i < 2; i++) {
                size_t aOff = (size_t)(rowBase + uRow[i]) * HID + k0 + uUnit[i] * 8;
                size_t bOff = (size_t)(colBase + uRow[i]) * HID + k0 + uUnit[i] * 8;
                pAh[i] = *(const uint4*)(Ahi + aOff);
                pAl[i] = *(const uint4*)(Alo + aOff);
                pBh[i] = *(const uint4*)(Bhi + bOff);
                pBl[i] = *(const uint4*)(Blo + bOff);
            }
        }

        // 2 x k16 steps
#pragma unroll
        for (int ks = 0; ks < 2; ks++) {
            uint32_t Ah[4][4], Al[4][4], Bh[2][4], Bl[2][4];
#pragma unroll
            for (int i = 0; i < 4; i++) {
                uint32_t off = aAddrBase[i] +
                    (uint32_t)(((ks * 2 + aUnitSel) ^ aMask[i]) << 4);
                ldmx4(Ah[i], sbase + O_AH + off);
                ldmx4(Al[i], sbase + O_AL + off);
            }
#pragma unroll
            for (int j2 = 0; j2 < 2; j2++) {
                uint32_t off = bAddrBase[j2] +
                    (uint32_t)(((ks * 2 + bUnitSel) ^ bMask[j2]) << 4);
                ldmx4(Bh[j2], sbase + O_BH + off);
                ldmx4(Bl[j2], sbase + O_BL + off);
            }
#pragma unroll
            for (int i = 0; i < 4; i++)
#pragma unroll
                for (int j = 0; j < 4; j++) {
                    const int g = j >> 1, p = (j & 1) * 2;
                    mma_bf16(c[i][j], Ah[i][0], Ah[i][1], Ah[i][2], Ah[i][3],
                             Bh[g][p], Bh[g][p + 1]);
                    mma_bf16(c[i][j], Ah[i][0], Ah[i][1], Ah[i][2], Ah[i][3],
                             Bl[g][p], Bl[g][p + 1]);
                    mma_bf16(c[i][j], Al[i][0], Al[i][1], Al[i][2], Al[i][3],
                             Bh[g][p], Bh[g][p + 1]);
                }
        }
        __syncthreads();
    }

    // epilogue (fragment layout: rows lq, lq+8; cols 2*lr, 2*lr+1)
    const int lq = lane >> 2;
    const int lr = lane & 3;
#pragma unroll
    for (int i = 0; i < 4; i++) {
        const int r0 = rowBase + wRow * 64 + i * 16 + lq;
#pragma unroll
        for (int j = 0; j < 4; j++) {
            const int cc = colBase + wCol * 32 + j * 8 + 2 * lr;
            if (SRC == 0) {
#pragma unroll
                for (int e = 0; e < 4; e++) {
                    const int r = r0 + (e >> 1) * 8;
                    const int col = cc + (e & 1);
                    const float v = c[i][j][e] + bias[col];
                    const int s = r >> 1;       // BATCH == 2
                    const int b = r & 1;
                    const int h = col / 384;
                    const int jj = col - h * 384;
                    const int which = jj >> 7;  // 0=q, 1=k, 2=v
                    const int dd = jj & 127;
                    float* dst = (which == 0) ? g_q : (which == 1 ? g_k : g_v);
                    dst[(size_t)(((b * NH + h) * S_LEN) + s) * HD + dd] = v;
                }
            } else {
                float2 v0 = make_float2(c[i][j][0], c[i][j][1]);
                float2 v1 = make_float2(c[i][j][2], c[i][j][3]);
                *(float2*)(out + (size_t)r0 * NDIM + cc) = v0;
                *(float2*)(out + (size_t)(r0 + 8) * NDIM + cc) = v1;
            }
        }
    }
}

// ---------------------------------------------------------------------------
// Flash attention (known-good): block = (b, h, 64-query tile), online softmax
// ---------------------------------------------------------------------------
#define BQ 64
#define BKT 64
#define QSTR 132
#define PSTR 68
#define NQT (S_LEN / BQ)
#define ATTN_SMEM ((BQ * QSTR * 3 + BQ * PSTR) * 4)

__global__ __launch_bounds__(256) void attn_kernel(
    const unsigned char* __restrict__ mask)
{
    extern __shared__ float sm[];
    float* sQ = sm;
    float* sK = sQ + BQ * QSTR;
    float* sV = sK + BKT * QSTR;
    float* sP = sV + BKT * QSTR;

    const int bid = blockIdx.x;
    const int qt = NQT - 1 - (bid % NQT);
    const int bh = bid / NQT;
    const int b = bh / NH;
    const int h = bh % NH;
    const int q0 = qt * BQ;

    const int tid = threadIdx.x;
    const int ty = tid >> 4, tx = tid & 15;
    const float inv_norm = 0.08838834764831845f;

    {
        const float* Qg = g_q + ((size_t)bh * S_LEN + q0) * HD;
#pragma unroll
        for (int it = 0; it < 8; ++it) {
            int e = tid + it * 256;
            int row = e >> 5;
            int c4 = (e & 31) * 4;
            *(float4*)&sQ[row * QSTR + c4] = *(const float4*)&Qg[row * HD + c4];
        }
    }

    float m_i[4], l_i[4], o[4][8];
#pragma unroll
    for (int ii = 0; ii < 4; ii++) {
        m_i[ii] = -1e30f; l_i[ii] = 0.0f;
#pragma unroll
        for (int cc = 0; cc < 8; cc++) o[ii][cc] = 0.0f;
    }

    for (int kt = 0; kt <= qt; ++kt) {
        const int k0 = kt * BKT;
        __syncthreads();
        {
            const float* Kg = g_k + ((size_t)bh * S_LEN + k0) * HD;
            const float* Vg = g_v + ((size_t)bh * S_LEN + k0) * HD;
#pragma unroll
            for (int it = 0; it < 8; ++it) {
                int e = tid + it * 256;
                int row = e >> 5;
                int c4 = (e & 31) * 4;
                *(float4*)&sK[row * QSTR + c4] = *(const float4*)&Kg[row * HD + c4];
                *(float4*)&sV[row * QSTR + c4] = *(const float4*)&Vg[row * HD + c4];
            }
        }
        __syncthreads();

        float acc[4][4];
#pragma unroll
        for (int ii = 0; ii < 4; ii++)
#pragma unroll
            for (int jj = 0; jj < 4; jj++) acc[ii][jj] = 0.0f;

        const float4* q4 = (const float4*)sQ;
        const float4* k4 = (const float4*)sK;
#pragma unroll 8
        for (int d4 = 0; d4 < 32; ++d4) {
            float4 qv[4], kv[4];
#pragma unroll
            for (int ii = 0; ii < 4; ii++) qv[ii] = q4[(ty * 4 + ii) * 33 + d4];
#pragma unroll
            for (int jj = 0; jj < 4; jj++) kv[jj] = k4[(tx * 4 + jj) * 33 + d4];
#pragma unroll
            for (int ii = 0; ii < 4; ii++)
#pragma unroll
                for (int jj = 0; jj < 4; jj++) {
                    acc[ii][jj] = fmaf(qv[ii].x, kv[jj].x, acc[ii][jj]);
                    acc[ii][jj] = fmaf(qv[ii].y, kv[jj].y, acc[ii][jj]);
                    acc[ii][jj] = fmaf(qv[ii].z, kv[jj].z, acc[ii][jj]);
                    acc[ii][jj] = fmaf(qv[ii].w, kv[jj].w, acc[ii][jj]);
                }
        }

#pragma unroll
        for (int ii = 0; ii < 4; ii++) {
            const int sg = q0 + ty * 4 + ii;
            const unsigned char* mrow = mask + ((size_t)b * S_LEN + sg) * S_LEN + k0;
            float vmax = -1e30f;
#pragma unroll
            for (int jj = 0; jj < 4; jj++) {
                const int tl = tx * 4 + jj;
                const int tg = k0 + tl;
                const bool masked = (tg > sg) || (mrow[tl] != 0);
                const float sval = masked ? -10000.0f : acc[ii][jj] * inv_norm;
                acc[ii][jj] = sval;
                vmax = fmaxf(vmax, sval);
            }
#pragma unroll
            for (int off = 8; off >= 1; off >>= 1)
                vmax = fmaxf(vmax, __shfl_xor_sync(0xffffffffu, vmax, off, 16));
            const float m_new = fmaxf(m_i[ii], vmax);
            const float corr = __expf(m_i[ii] - m_new);
            float lsum = 0.0f;
#pragma unroll
            for (int jj = 0; jj < 4; jj++) {
                const float p = __expf(acc[ii][jj] - m_new);
                lsum += p;
                sP[(ty * 4 + ii) * PSTR + tx * 4 + jj] = p;
            }
#pragma unroll
            for (int off = 8; off >= 1; off >>= 1)
                lsum += __shfl_xor_sync(0xffffffffu, lsum, off, 16);
            l_i[ii] = l_i[ii] * corr + lsum;
            m_i[ii] = m_new;
#pragma unroll
            for (int cc = 0; cc < 8; cc++) o[ii][cc] *= corr;
        }
        __syncthreads();

        const float4* v4 = (const float4*)sV;
#pragma unroll 4
        for (int j = 0; j < BKT; ++j) {
            const float4 va = v4[j * 33 + tx * 2];
            const float4 vb = v4[j * 33 + tx * 2 + 1];
#pragma unroll
            for (int ii = 0; ii < 4; ii++) {
                const float p = sP[(ty * 4 + ii) * PSTR + j];
                o[ii][0] = fmaf(p, va.x, o[ii][0]);
                o[ii][1] = fmaf(p, va.y, o[ii][1]);
                o[ii][2] = fmaf(p, va.z, o[ii][2]);
                o[ii][3] = fmaf(p, va.w, o[ii][3]);
                o[ii][4] = fmaf(p, vb.x, o[ii][4]);
                o[ii][5] = fmaf(p, vb.y, o[ii][5]);
                o[ii][6] = fmaf(p, vb.z, o[ii][6]);
                o[ii][7] = fmaf(p, vb.w, o[ii][7]);
            }
        }
    }

#pragma unroll
    for (int ii = 0; ii < 4; ii++) {
        const int sg = q0 + ty * 4 + ii;
        const float inv_l = 1.0f / l_i[ii];
        float* dst = g_ctx + ((size_t)sg * BATCH + b) * HID + h * HD + tx * 8;
        float4 r0, r1;
        r0.x = o[ii][0] * inv_l; r0.y = o[ii][1] * inv_l;
        r0.z = o[ii][2] * inv_l; r0.w = o[ii][3] * inv_l;
        r1.x = o[ii][4] * inv_l; r1.y = o[ii][5] * inv_l;
        r1.z = o[ii][6] * inv_l; r1.w = o[ii][7] * inv_l;
        *(float4*)dst = r0;
        *(float4*)(dst + 4) = r1;
    }
}

__global__ void copy_bias_kernel(const float* __restrict__ bias, float* __restrict__ dst)
{
    int i = blockIdx.x * blockDim.x + threadIdx.x;
    if (i < HID) dst[i] = bias[i];
}

// ---------------------------------------------------------------------------
extern "C" void kernel_launch(void* const* d_in, const int* in_sizes, int n_in,
                              void* d_out, int out_size)
{
    const float* hidden   = (const float*)d_in[0];
    const unsigned char* mask = (const unsigned char*)d_in[1];
    const float* qkv_w    = (const float*)d_in[2];
    const float* qkv_b    = (const float*)d_in[3];
    const float* proj_w   = (const float*)d_in[4];
    const float* proj_b   = (const float*)d_in[5];
    float* out = (float*)d_out;

    cudaFuncSetAttribute(attn_kernel,
                         cudaFuncAttributeMaxDynamicSharedMemorySize, ATTN_SMEM);

    // 1. input splits (bandwidth-bound prep)
    split_hidden_kernel<<<M_ROWS * HID / 256, 256>>>(hidden);
    transpose_split_kernel<N3H, 0><<<dim3(N3H / 32, HID / 32), dim3(32, 8)>>>(qkv_w);
    transpose_split_kernel<HID, 1><<<dim3(HID / 32, HID / 32), dim3(32, 8)>>>(proj_w);

    // 2. QKV GEMM (bf16x3 HMMA)
    gemm_hmma_kernel<N3H, 0><<<dim3(N3H / 128, M_ROWS / 128), 256>>>(qkv_b, nullptr);

    // 3. attention
    attn_kernel<<<BATCH * NH * NQT, 256, ATTN_SMEM>>>(mask);

    // 4. ctx split + proj GEMM
    split_ctx_kernel<<<M_ROWS * HID / 256, 256>>>();
    gemm_hmma_kernel<HID, 1><<<dim3(HID / 128, M_ROWS / 128), 256>>>(nullptr, out);

    if (out_size > M_ROWS * HID) {
        copy_bias_kernel<<<(HID + 255) / 256, 256>>>(proj_b, out + (size_t)M_ROWS * HID);
    }
}

// round 7
// speedup vs baseline: 3.7078x; 1.8443x over previous
#include <cuda_runtime.h>
#include <cuda_bf16.h>
#include <math.h>
#include <stdint.h>

#define S_LEN 2048
#define BATCH 2
#define HID   2048
#define NH    16
#define HD    128
#define M_ROWS (S_LEN * BATCH)   // 4096
#define N3H    (3 * HID)         // 6144
#define NBH    (BATCH * NH)      // 32

// ---------------------------------------------------------------------------
// Device-global scratch (allocation-free). All attention operands bf16 hi/lo.
// ---------------------------------------------------------------------------
__device__ __nv_bfloat16 g_qh[NBH * S_LEN * HD];
__device__ __nv_bfloat16 g_ql[NBH * S_LEN * HD];
__device__ __nv_bfloat16 g_kh[NBH * S_LEN * HD];
__device__ __nv_bfloat16 g_kl[NBH * S_LEN * HD];
__device__ __nv_bfloat16 g_vh[NBH * S_LEN * HD];
__device__ __nv_bfloat16 g_vl[NBH * S_LEN * HD];
__device__ __nv_bfloat16 g_chi[M_ROWS * HID];
__device__ __nv_bfloat16 g_clo[M_ROWS * HID];

__device__ __nv_bfloat16 g_ahi[M_ROWS * HID];       // hidden split
__device__ __nv_bfloat16 g_alo[M_ROWS * HID];
__device__ __nv_bfloat16 g_wqh[(size_t)N3H * HID];  // qkv_w^T split
__device__ __nv_bfloat16 g_wql[(size_t)N3H * HID];
__device__ __nv_bfloat16 g_wph[(size_t)HID * HID];  // proj_w^T split
__device__ __nv_bfloat16 g_wpl[(size_t)HID * HID];

// ---------------------------------------------------------------------------
// MMA / ldmatrix helpers
// ---------------------------------------------------------------------------
__device__ __forceinline__ uint32_t smem_u32(const void* p) {
    uint32_t a;
    asm("{ .reg .u64 t; cvta.to.shared.u64 t, %1; cvt.u32.u64 %0, t; }"
        : "=r"(a) : "l"(p));
    return a;
}
__device__ __forceinline__ void ldmx4(uint32_t r[4], uint32_t addr) {
    asm volatile("ldmatrix.sync.aligned.m8n8.x4.shared.b16 {%0,%1,%2,%3}, [%4];"
                 : "=r"(r[0]), "=r"(r[1]), "=r"(r[2]), "=r"(r[3]) : "r"(addr));
}
__device__ __forceinline__ void ldmx4t(uint32_t r[4], uint32_t addr) {
    asm volatile("ldmatrix.sync.aligned.m8n8.x4.trans.shared.b16 {%0,%1,%2,%3}, [%4];"
                 : "=r"(r[0]), "=r"(r[1]), "=r"(r[2]), "=r"(r[3]) : "r"(addr));
}
__device__ __forceinline__ void mma_bf16(float c[4],
                                         uint32_t a0, uint32_t a1, uint32_t a2, uint32_t a3,
                                         uint32_t b0, uint32_t b1) {
    asm volatile(
        "mma.sync.aligned.m16n8k16.row.col.f32.bf16.bf16.f32 "
        "{%0,%1,%2,%3}, {%4,%5,%6,%7}, {%8,%9}, {%0,%1,%2,%3};"
        : "+f"(c[0]), "+f"(c[1]), "+f"(c[2]), "+f"(c[3])
        : "r"(a0), "r"(a1), "r"(a2), "r"(a3), "r"(b0), "r"(b1));
}

// ---------------------------------------------------------------------------
// Split prep kernels
// ---------------------------------------------------------------------------
__global__ void split_hidden_kernel(const float* __restrict__ in)
{
    int i = blockIdx.x * blockDim.x + threadIdx.x;
    float x = in[i];
    __nv_bfloat16 h = __float2bfloat16(x);
    g_ahi[i] = h;
    g_alo[i] = __float2bfloat16(x - __bfloat162float(h));
}

template<int NIN, int WSEL>
__global__ void transpose_split_kernel(const float* __restrict__ W)
{
    __shared__ float s[32][33];
    const int tx = threadIdx.x, ty = threadIdx.y;
    const int n0 = blockIdx.x * 32, k0 = blockIdx.y * 32;
    __nv_bfloat16* outHi = (WSEL == 0) ? g_wqh : g_wph;
    __nv_bfloat16* outLo = (WSEL == 0) ? g_wql : g_wpl;
#pragma unroll
    for (int i = 0; i < 4; i++) {
        int k = k0 + ty + i * 8;
        s[ty + i * 8][tx] = W[(size_t)k * NIN + n0 + tx];
    }
    __syncthreads();
#pragma unroll
    for (int i = 0; i < 4; i++) {
        int n = n0 + ty + i * 8;
        int k = k0 + tx;
        float x = s[tx][ty + i * 8];
        __nv_bfloat16 h = __float2bfloat16(x);
        outHi[(size_t)n * HID + k] = h;
        outLo[(size_t)n * HID + k] = __float2bfloat16(x - __bfloat162float(h));
    }
}

// ---------------------------------------------------------------------------
// bf16x3 HMMA GEMM (validated R6). SRC 0: QKV (epilogue -> bf16 hi/lo q/k/v).
// SRC 1: proj (A = g_chi/g_clo, epilogue -> fp32 out).
// ---------------------------------------------------------------------------
#define TILE_BYTES 8192
#define O_AH 0
#define O_AL 8192
#define O_BH 16384
#define O_BL 24576

__device__ __forceinline__ uint32_t swz_off(int row, int unit) {
    return (uint32_t)(row * 64 + ((unit ^ ((row >> 1) & 3)) << 4));
}

template<int NDIM, int SRC>
__global__ __launch_bounds__(256) void gemm_hmma_kernel(
    const float* __restrict__ bias, float* __restrict__ out)
{
    __shared__ char smem[4 * TILE_BYTES];
    const uint32_t sbase = smem_u32(smem);

    const int tid  = threadIdx.x;
    const int lane = tid & 31;
    const int wid  = tid >> 5;
    const int wRow = wid >> 2;
    const int wCol = wid & 3;
    const int rowBase = blockIdx.y * 128;
    const int colBase = blockIdx.x * 128;

    const __nv_bfloat16* Ahi = (SRC == 0) ? g_ahi : g_chi;
    const __nv_bfloat16* Alo = (SRC == 0) ? g_alo : g_clo;
    const __nv_bfloat16* Bhi = (SRC == 0) ? g_wqh : g_wph;
    const __nv_bfloat16* Blo = (SRC == 0) ? g_wql : g_wpl;

    float c[4][4][4];
#pragma unroll
    for (int i = 0; i < 4; i++)
#pragma unroll
        for (int j = 0; j < 4; j++)
#pragma unroll
            for (int e = 0; e < 4; e++) c[i][j][e] = 0.0f;

    int uRow[2], uUnit[2];
    uint32_t uSwz[2];
#pragma unroll
    for (int i = 0; i < 2; i++) {
        int u = tid + i * 256;
        uRow[i]  = u >> 2;
        uUnit[i] = u & 3;
        uSwz[i]  = swz_off(uRow[i], uUnit[i]);
    }

    const int aRowLane  = lane & 15;
    const int aUnitSel  = lane >> 4;
    const int bRowLane  = (lane & 7) + ((lane >> 4) & 1) * 8;
    const int bUnitSel  = (lane >> 3) & 1;

    uint32_t aAddrBase[4], bAddrBase[2];
    int aMask[4], bMask[2];
#pragma unroll
    for (int i = 0; i < 4; i++) {
        int r = wRow * 64 + i * 16 + aRowLane;
        aMask[i] = (r >> 1) & 3;
        aAddrBase[i] = (uint32_t)(r * 64);
    }
#pragma unroll
    for (int j2 = 0; j2 < 2; j2++) {
        int r = wCol * 32 + j2 * 16 + bRowLane;
        bMask[j2] = (r >> 1) & 3;
        bAddrBase[j2] = (uint32_t)(r * 64);
    }

    const int NIT = HID / 32;
    uint4 pAh[2], pAl[2], pBh[2], pBl[2];
#pragma unroll
    for (int i = 0; i < 2; i++) {
        size_t aOff = (size_t)(rowBase + uRow[i]) * HID + uUnit[i] * 8;
        size_t bOff = (size_t)(colBase + uRow[i]) * HID + uUnit[i] * 8;
        pAh[i] = *(const uint4*)(Ahi + aOff);
        pAl[i] = *(const uint4*)(Alo + aOff);
        pBh[i] = *(const uint4*)(Bhi + bOff);
        pBl[i] = *(const uint4*)(Blo + bOff);
    }

    for (int it = 0; it < NIT; ++it) {
#pragma unroll
        for (int i = 0; i < 2; i++) {
            *(uint4*)(smem + O_AH + uSwz[i]) = pAh[i];
            *(uint4*)(smem + O_AL + uSwz[i]) = pAl[i];
            *(uint4*)(smem + O_BH + uSwz[i]) = pBh[i];
            *(uint4*)(smem + O_BL + uSwz[i]) = pBl[i];
        }
        __syncthreads();

        if (it + 1 < NIT) {
            const int k0 = (it + 1) * 32;
#pragma unroll
            for (int i = 0; i < 2; i++) {
                size_t aOff = (size_t)(rowBase + uRow[i]) * HID + k0 + uUnit[i] * 8;
                size_t bOff = (size_t)(colBase + uRow[i]) * HID + k0 + uUnit[i] * 8;
                pAh[i] = *(const uint4*)(Ahi + aOff);
                pAl[i] = *(const uint4*)(Alo + aOff);
                pBh[i] = *(const uint4*)(Bhi + bOff);
                pBl[i] = *(const uint4*)(Blo + bOff);
            }
        }

#pragma unroll
        for (int ks = 0; ks < 2; ks++) {
            uint32_t Ah[4][4], Al[4][4], Bh[2][4], Bl[2][4];
#pragma unroll
            for (int i = 0; i < 4; i++) {
                uint32_t off = aAddrBase[i] +
                    (uint32_t)(((ks * 2 + aUnitSel) ^ aMask[i]) << 4);
                ldmx4(Ah[i], sbase + O_AH + off);
                ldmx4(Al[i], sbase + O_AL + off);
            }
#pragma unroll
            for (int j2 = 0; j2 < 2; j2++) {
                uint32_t off = bAddrBase[j2] +
                    (uint32_t)(((ks * 2 + bUnitSel) ^ bMask[j2]) << 4);
                ldmx4(Bh[j2], sbase + O_BH + off);
                ldmx4(Bl[j2], sbase + O_BL + off);
            }
#pragma unroll
            for (int i = 0; i < 4; i++)
#pragma unroll
                for (int j = 0; j < 4; j++) {
                    const int g = j >> 1, p = (j & 1) * 2;
                    mma_bf16(c[i][j], Ah[i][0], Ah[i][1], Ah[i][2], Ah[i][3],
                             Bh[g][p], Bh[g][p + 1]);
                    mma_bf16(c[i][j], Ah[i][0], Ah[i][1], Ah[i][2], Ah[i][3],
                             Bl[g][p], Bl[g][p + 1]);
                    mma_bf16(c[i][j], Al[i][0], Al[i][1], Al[i][2], Al[i][3],
                             Bh[g][p], Bh[g][p + 1]);
                }
        }
        __syncthreads();
    }

    const int lq = lane >> 2;
    const int lr = lane & 3;
#pragma unroll
    for (int i = 0; i < 4; i++) {
        const int r0 = rowBase + wRow * 64 + i * 16 + lq;
#pragma unroll
        for (int j = 0; j < 4; j++) {
            const int cc = colBase + wCol * 32 + j * 8 + 2 * lr;
            if (SRC == 0) {
#pragma unroll
                for (int e = 0; e < 4; e++) {
                    const int r = r0 + (e >> 1) * 8;
                    const int col = cc + (e & 1);
                    const float v = c[i][j][e] + bias[col];
                    const int s = r >> 1;       // BATCH == 2
                    const int b = r & 1;
                    const int h = col / 384;
                    const int jj = col - h * 384;
                    const int which = jj >> 7;  // 0=q, 1=k, 2=v
                    const int dd = jj & 127;
                    __nv_bfloat16* ph = (which == 0) ? g_qh : (which == 1 ? g_kh : g_vh);
                    __nv_bfloat16* pl = (which == 0) ? g_ql : (which == 1 ? g_kl : g_vl);
                    const size_t idx = (size_t)(((b * NH + h) * S_LEN) + s) * HD + dd;
                    __nv_bfloat16 hh = __float2bfloat16(v);
                    ph[idx] = hh;
                    pl[idx] = __float2bfloat16(v - __bfloat162float(hh));
                }
            } else {
                float2 v0 = make_float2(c[i][j][0], c[i][j][1]);
                float2 v1 = make_float2(c[i][j][2], c[i][j][3]);
                *(float2*)(out + (size_t)r0 * NDIM + cc) = v0;
                *(float2*)(out + (size_t)(r0 + 8) * NDIM + cc) = v1;
            }
        }
    }
}

// ---------------------------------------------------------------------------
// MMA flash attention. Block = (b,h,64-row q tile), 128 threads = 4 warps,
// warp owns 16 FULL rows of S (softmax needs only quad shuffles).
// S = QK^T and O += P V on HMMA with bf16 hi/lo 3-term splits.
// ---------------------------------------------------------------------------
#define ATQ 64
#define NQT (S_LEN / ATQ)        // 32
#define A_SMEM (6 * 16384)       // Qh,Ql,Kh,Kl,Vh,Vl tiles (64x128 bf16 each)
#define SQ_H 0
#define SQ_L 16384
#define SK_H 32768
#define SK_L 49152
#define SV_H 65536
#define SV_L 81920

// 256B rows (16 x 16B units); xor-swizzle with (row&7)
__device__ __forceinline__ uint32_t soff(int row, int unit) {
    return (uint32_t)(row * 256 + ((unit ^ (row & 7)) << 4));
}

__global__ __launch_bounds__(128) void attn_mma_kernel(
    const unsigned char* __restrict__ mask)
{
    extern __shared__ char sm8[];
    const uint32_t sb = smem_u32(sm8);

    const int bid = blockIdx.x;
    const int qt = NQT - 1 - (bid % NQT);    // heavy tiles first
    const int bh = bid / NQT;
    const int b = bh / NH;
    const int h = bh % NH;
    const int q0 = qt * ATQ;

    const int tid = threadIdx.x;
    const int lane = tid & 31;
    const int w = tid >> 5;                  // warp 0..3 -> rows w*16..
    const int lq = lane >> 2;
    const int lr = lane & 3;
    const float inv_norm = 0.08838834764831845f;  // 1/sqrt(128)

    // Load Q tile (64x128 bf16 hi/lo)
    {
        const __nv_bfloat16* Qh = g_qh + ((size_t)bh * S_LEN + q0) * HD;
        const __nv_bfloat16* Ql = g_ql + ((size_t)bh * S_LEN + q0) * HD;
#pragma unroll
        for (int i = 0; i < 8; i++) {
            int u = tid + i * 128;
            int row = u >> 4, un = u & 15;
            uint32_t off = soff(row, un);
            *(uint4*)(sm8 + SQ_H + off) = ((const uint4*)(Qh + row * HD))[un];
            *(uint4*)(sm8 + SQ_L + off) = ((const uint4*)(Ql + row * HD))[un];
        }
    }

    const int sg0 = q0 + w * 16 + lq;
    const int sg1 = sg0 + 8;
    const unsigned char* mrow0 = mask + ((size_t)b * S_LEN + sg0) * S_LEN;
    const unsigned char* mrow1 = mask + ((size_t)b * S_LEN + sg1) * S_LEN;

    float m0 = -1e30f, m1 = -1e30f, l0 = 0.0f, l1 = 0.0f;
    float o[16][4];
#pragma unroll
    for (int jd = 0; jd < 16; jd++)
#pragma unroll
        for (int e = 0; e < 4; e++) o[jd][e] = 0.0f;

    for (int kt = 0; kt <= qt; ++kt) {
        const int k0 = kt * ATQ;
        __syncthreads();
        {
            const __nv_bfloat16* Kh = g_kh + ((size_t)bh * S_LEN + k0) * HD;
            const __nv_bfloat16* Kl = g_kl + ((size_t)bh * S_LEN + k0) * HD;
            const __nv_bfloat16* Vh = g_vh + ((size_t)bh * S_LEN + k0) * HD;
            const __nv_bfloat16* Vl = g_vl + ((size_t)bh * S_LEN + k0) * HD;
#pragma unroll
            for (int i = 0; i < 8; i++) {
                int u = tid + i * 128;
                int row = u >> 4, un = u & 15;
                uint32_t off = soff(row, un);
                *(uint4*)(sm8 + SK_H + off) = ((const uint4*)(Kh + row * HD))[un];
                *(uint4*)(sm8 + SK_L + off) = ((const uint4*)(Kl + row * HD))[un];
                *(uint4*)(sm8 + SV_H + off) = ((const uint4*)(Vh + row * HD))[un];
                *(uint4*)(sm8 + SV_L + off) = ((const uint4*)(Vl + row * HD))[un];
            }
        }
        __syncthreads();

        // ---- S = Q K^T (64 cols, 8 n8-tiles per warp-row-strip)
        float c[8][4];
#pragma unroll
        for (int j = 0; j < 8; j++)
#pragma unroll
            for (int e = 0; e < 4; e++) c[j][e] = 0.0f;

#pragma unroll
        for (int ks = 0; ks < 8; ks++) {
            uint32_t qh4[4], ql4[4];
            {
                int r = w * 16 + (lane & 15);
                int un = ks * 2 + (lane >> 4);
                uint32_t off = soff(r, un);
                ldmx4(qh4, sb + SQ_H + off);
                ldmx4(ql4, sb + SQ_L + off);
            }
#pragma unroll
            for (int nt = 0; nt < 4; nt++) {
                int r = nt * 16 + (lane & 7) + ((lane >> 4) & 1) * 8;
                int un = ks * 2 + ((lane >> 3) & 1);
                uint32_t off = soff(r, un);
                uint32_t kh4[4], kl4[4];
                ldmx4(kh4, sb + SK_H + off);
                ldmx4(kl4, sb + SK_L + off);
                mma_bf16(c[2 * nt], qh4[0], qh4[1], qh4[2], qh4[3], kh4[0], kh4[1]);
                mma_bf16(c[2 * nt], qh4[0], qh4[1], qh4[2], qh4[3], kl4[0], kl4[1]);
                mma_bf16(c[2 * nt], ql4[0], ql4[1], ql4[2], ql4[3], kh4[0], kh4[1]);
                mma_bf16(c[2 * nt + 1], qh4[0], qh4[1], qh4[2], qh4[3], kh4[2], kh4[3]);
                mma_bf16(c[2 * nt + 1], qh4[0], qh4[1], qh4[2], qh4[3], kl4[2], kl4[3]);
                mma_bf16(c[2 * nt + 1], ql4[0], ql4[1], ql4[2], ql4[3], kh4[2], kh4[3]);
            }
        }

        // ---- scale + mask
#pragma unroll
        for (int j = 0; j < 8; j++) {
            const int t0 = k0 + j * 8 + 2 * lr;
            uchar2 mb0 = *(const uchar2*)(mrow0 + t0);
            uchar2 mb1 = *(const uchar2*)(mrow1 + t0);
            c[j][0] = (t0 > sg0     || mb0.x) ? -10000.0f : c[j][0] * inv_norm;
            c[j][1] = (t0 + 1 > sg0 || mb0.y) ? -10000.0f : c[j][1] * inv_norm;
            c[j][2] = (t0 > sg1     || mb1.x) ? -10000.0f : c[j][2] * inv_norm;
            c[j][3] = (t0 + 1 > sg1 || mb1.y) ? -10000.0f : c[j][3] * inv_norm;
        }

        // ---- online softmax (quad shuffles only)
        float vm0 = -1e30f, vm1 = -1e30f;
#pragma unroll
        for (int j = 0; j < 8; j++) {
            vm0 = fmaxf(vm0, fmaxf(c[j][0], c[j][1]));
            vm1 = fmaxf(vm1, fmaxf(c[j][2], c[j][3]));
        }
        vm0 = fmaxf(vm0, __shfl_xor_sync(0xffffffffu, vm0, 1));
        vm0 = fmaxf(vm0, __shfl_xor_sync(0xffffffffu, vm0, 2));
        vm1 = fmaxf(vm1, __shfl_xor_sync(0xffffffffu, vm1, 1));
        vm1 = fmaxf(vm1, __shfl_xor_sync(0xffffffffu, vm1, 2));
        const float mn0 = fmaxf(m0, vm0), mn1 = fmaxf(m1, vm1);
        const float cor0 = __expf(m0 - mn0), cor1 = __expf(m1 - mn1);
        m0 = mn0; m1 = mn1;

        uint32_t aPh[8][2], aPl[8][2];
        float ls0 = 0.0f, ls1 = 0.0f;
#pragma unroll
        for (int j = 0; j < 8; j++) {
            float p0 = __expf(c[j][0] - mn0);
            float p1 = __expf(c[j][1] - mn0);
            float p2 = __expf(c[j][2] - mn1);
            float p3 = __expf(c[j][3] - mn1);
            ls0 += p0 + p1; ls1 += p2 + p3;
            __nv_bfloat162 h01 = __floats2bfloat162_rn(p0, p1);
            __nv_bfloat162 h23 = __floats2bfloat162_rn(p2, p3);
            __nv_bfloat162 l01 = __floats2bfloat162_rn(
                p0 - __bfloat162float(h01.x), p1 - __bfloat162float(h01.y));
            __nv_bfloat162 l23 = __floats2bfloat162_rn(
                p2 - __bfloat162float(h23.x), p3 - __bfloat162float(h23.y));
            aPh[j][0] = *(uint32_t*)&h01;
            aPh[j][1] = *(uint32_t*)&h23;
            aPl[j][0] = *(uint32_t*)&l01;
            aPl[j][1] = *(uint32_t*)&l23;
        }
        l0 = l0 * cor0 + ls0;
        l1 = l1 * cor1 + ls1;
#pragma unroll
        for (int jd = 0; jd < 16; jd++) {
            o[jd][0] *= cor0; o[jd][1] *= cor0;
            o[jd][2] *= cor1; o[jd][3] *= cor1;
        }

        // ---- O += P V  (V fragments via ldmatrix.trans)
#pragma unroll
        for (int ss = 0; ss < 4; ss++) {
            const uint32_t ah0 = aPh[2 * ss][0], ah1 = aPh[2 * ss][1];
            const uint32_t ah2 = aPh[2 * ss + 1][0], ah3 = aPh[2 * ss + 1][1];
            const uint32_t al0 = aPl[2 * ss][0], al1 = aPl[2 * ss][1];
            const uint32_t al2 = aPl[2 * ss + 1][0], al3 = aPl[2 * ss + 1][1];
            int r = ss * 16 + (lane & 7) + ((lane >> 3) & 1) * 8;
#pragma unroll
            for (int dt = 0; dt < 8; dt++) {
                int un = dt * 2 + ((lane >> 4) & 1);
                uint32_t off = soff(r, un);
                uint32_t vh4[4], vl4[4];
                ldmx4t(vh4, sb + SV_H + off);
                ldmx4t(vl4, sb + SV_L + off);
                mma_bf16(o[2 * dt], ah0, ah1, ah2, ah3, vh4[0], vh4[1]);
                mma_bf16(o[2 * dt], ah0, ah1, ah2, ah3, vl4[0], vl4[1]);
                mma_bf16(o[2 * dt], al0, al1, al2, al3, vh4[0], vh4[1]);
                mma_bf16(o[2 * dt + 1], ah0, ah1, ah2, ah3, vh4[2], vh4[3]);
                mma_bf16(o[2 * dt + 1], ah0, ah1, ah2, ah3, vl4[2], vl4[3]);
                mma_bf16(o[2 * dt + 1], al0, al1, al2, al3, vh4[2], vh4[3]);
            }
        }
    }

    // ---- finalize: reduce l over quad, normalize, write ctx bf16 hi/lo
    l0 += __shfl_xor_sync(0xffffffffu, l0, 1);
    l0 += __shfl_xor_sync(0xffffffffu, l0, 2);
    l1 += __shfl_xor_sync(0xffffffffu, l1, 1);
    l1 += __shfl_xor_sync(0xffffffffu, l1, 2);
    const float inv0 = 1.0f / l0, inv1 = 1.0f / l1;

    __nv_bfloat16* chiBase = g_chi + (size_t)h * HD;
    __nv_bfloat16* cloBase = g_clo + (size_t)h * HD;
    const size_t row0 = (size_t)(sg0 * BATCH + b) * HID;
    const size_t row1 = (size_t)(sg1 * BATCH + b) * HID;
#pragma unroll
    for (int jd = 0; jd < 16; jd++) {
        const int d = jd * 8 + 2 * lr;
        float v0 = o[jd][0] * inv0, v1 = o[jd][1] * inv0;
        float v2 = o[jd][2] * inv1, v3 = o[jd][3] * inv1;
        __nv_bfloat162 h01 = __floats2bfloat162_rn(v0, v1);
        __nv_bfloat162 l01 = __floats2bfloat162_rn(
            v0 - __bfloat162float(h01.x), v1 - __bfloat162float(h01.y));
        __nv_bfloat162 h23 = __floats2bfloat162_rn(v2, v3);
        __nv_bfloat162 l23 = __floats2bfloat162_rn(
            v2 - __bfloat162float(h23.x), v3 - __bfloat162float(h23.y));
        *(__nv_bfloat162*)(chiBase + row0 + d) = h01;
        *(__nv_bfloat162*)(cloBase + row0 + d) = l01;
        *(__nv_bfloat162*)(chiBase + row1 + d) = h23;
        *(__nv_bfloat162*)(cloBase + row1 + d) = l23;
    }
}

__global__ void copy_bias_kernel(const float* __restrict__ bias, float* __restrict__ dst)
{
    int i = blockIdx.x * blockDim.x + threadIdx.x;
    if (i < HID) dst[i] = bias[i];
}

// ---------------------------------------------------------------------------
extern "C" void kernel_launch(void* const* d_in, const int* in_sizes, int n_in,
                              void* d_out, int out_size)
{
    const float* hidden   = (const float*)d_in[0];
    const unsigned char* mask = (const unsigned char*)d_in[1];
    const float* qkv_w    = (const float*)d_in[2];
    const float* qkv_b    = (const float*)d_in[3];
    const float* proj_w   = (const float*)d_in[4];
    const float* proj_b   = (const float*)d_in[5];
    float* out = (float*)d_out;

    cudaFuncSetAttribute(attn_mma_kernel,
                         cudaFuncAttributeMaxDynamicSharedMemorySize, A_SMEM);

    // 1. prep splits
    split_hidden_kernel<<<M_ROWS * HID / 256, 256>>>(hidden);
    transpose_split_kernel<N3H, 0><<<dim3(N3H / 32, HID / 32), dim3(32, 8)>>>(qkv_w);
    transpose_split_kernel<HID, 1><<<dim3(HID / 32, HID / 32), dim3(32, 8)>>>(proj_w);

    // 2. QKV GEMM -> bf16 hi/lo q/k/v
    gemm_hmma_kernel<N3H, 0><<<dim3(N3H / 128, M_ROWS / 128), 256>>>(qkv_b, nullptr);

    // 3. MMA flash attention -> bf16 hi/lo ctx
    attn_mma_kernel<<<NBH * NQT, 128, A_SMEM>>>(mask);

    // 4. proj GEMM -> out
    gemm_hmma_kernel<HID, 1><<<dim3(HID / 128, M_ROWS / 128), 256>>>(nullptr, out);

    if (out_size > M_ROWS * HID) {
        copy_bias_kernel<<<(HID + 255) / 256, 256>>>(proj_b, out + (size_t)M_ROWS * HID);
    }
}

// round 11
// speedup vs baseline: 4.7348x; 1.2770x over previous
#include <cuda_runtime.h>
#include <cuda_bf16.h>
#include <math.h>
#include <stdint.h>

#define S_LEN 2048
#define BATCH 2
#define HID   2048
#define NH    16
#define HD    128
#define M_ROWS (S_LEN * BATCH)   // 4096
#define N3H    (3 * HID)         // 6144
#define NBH    (BATCH * NH)      // 32

// ---------------------------------------------------------------------------
// Device-global scratch (allocation-free). All attention operands bf16 hi/lo.
// ---------------------------------------------------------------------------
__device__ __nv_bfloat16 g_qh[NBH * S_LEN * HD];
__device__ __nv_bfloat16 g_ql[NBH * S_LEN * HD];
__device__ __nv_bfloat16 g_kh[NBH * S_LEN * HD];
__device__ __nv_bfloat16 g_kl[NBH * S_LEN * HD];
__device__ __nv_bfloat16 g_vh[NBH * S_LEN * HD];
__device__ __nv_bfloat16 g_vl[NBH * S_LEN * HD];
__device__ __nv_bfloat16 g_chi[M_ROWS * HID];
__device__ __nv_bfloat16 g_clo[M_ROWS * HID];

__device__ __nv_bfloat16 g_ahi[M_ROWS * HID];       // hidden split
__device__ __nv_bfloat16 g_alo[M_ROWS * HID];
__device__ __nv_bfloat16 g_wqh[(size_t)N3H * HID];  // qkv_w^T split
__device__ __nv_bfloat16 g_wql[(size_t)N3H * HID];
__device__ __nv_bfloat16 g_wph[(size_t)HID * HID];  // proj_w^T split
__device__ __nv_bfloat16 g_wpl[(size_t)HID * HID];

// ---------------------------------------------------------------------------
// MMA / ldmatrix / cp.async helpers
// ---------------------------------------------------------------------------
__device__ __forceinline__ uint32_t smem_u32(const void* p) {
    uint32_t a;
    asm("{ .reg .u64 t; cvta.to.shared.u64 t, %1; cvt.u32.u64 %0, t; }"
        : "=r"(a) : "l"(p));
    return a;
}
__device__ __forceinline__ void ldmx4(uint32_t r[4], uint32_t addr) {
    asm volatile("ldmatrix.sync.aligned.m8n8.x4.shared.b16 {%0,%1,%2,%3}, [%4];"
                 : "=r"(r[0]), "=r"(r[1]), "=r"(r[2]), "=r"(r[3]) : "r"(addr));
}
__device__ __forceinline__ void ldmx4t(uint32_t r[4], uint32_t addr) {
    asm volatile("ldmatrix.sync.aligned.m8n8.x4.trans.shared.b16 {%0,%1,%2,%3}, [%4];"
                 : "=r"(r[0]), "=r"(r[1]), "=r"(r[2]), "=r"(r[3]) : "r"(addr));
}
__device__ __forceinline__ void mma_bf16(float c[4],
                                         uint32_t a0, uint32_t a1, uint32_t a2, uint32_t a3,
                                         uint32_t b0, uint32_t b1) {
    asm volatile(
        "mma.sync.aligned.m16n8k16.row.col.f32.bf16.bf16.f32 "
        "{%0,%1,%2,%3}, {%4,%5,%6,%7}, {%8,%9}, {%0,%1,%2,%3};"
        : "+f"(c[0]), "+f"(c[1]), "+f"(c[2]), "+f"(c[3])
        : "r"(a0), "r"(a1), "r"(a2), "r"(a3), "r"(b0), "r"(b1));
}
__device__ __forceinline__ void cp16(uint32_t saddr, const void* g) {
    asm volatile("cp.async.cg.shared.global [%0], [%1], 16;" :: "r"(saddr), "l"(g));
}
#define CP_COMMIT() asm volatile("cp.async.commit_group;" ::: "memory")
#define CP_WAIT(n)  asm volatile("cp.async.wait_group %0;" :: "n"(n) : "memory")

// ---------------------------------------------------------------------------
// Split prep kernels
// ---------------------------------------------------------------------------
__global__ void split_hidden_kernel(const float* __restrict__ in)
{
    int i = blockIdx.x * blockDim.x + threadIdx.x;
    float x = in[i];
    __nv_bfloat16 h = __float2bfloat16(x);
    g_ahi[i] = h;
    g_alo[i] = __float2bfloat16(x - __bfloat162float(h));
}

template<int NIN, int WSEL>
__global__ void transpose_split_kernel(const float* __restrict__ W)
{
    __shared__ float s[32][33];
    const int tx = threadIdx.x, ty = threadIdx.y;
    const int n0 = blockIdx.x * 32, k0 = blockIdx.y * 32;
    __nv_bfloat16* outHi = (WSEL == 0) ? g_wqh : g_wph;
    __nv_bfloat16* outLo = (WSEL == 0) ? g_wql : g_wpl;
#pragma unroll
    for (int i = 0; i < 4; i++) {
        int k = k0 + ty + i * 8;
        s[ty + i * 8][tx] = W[(size_t)k * NIN + n0 + tx];
    }
    __syncthreads();
#pragma unroll
    for (int i = 0; i < 4; i++) {
        int n = n0 + ty + i * 8;
        int k = k0 + tx;
        float x = s[tx][ty + i * 8];
        __nv_bfloat16 h = __float2bfloat16(x);
        outHi[(size_t)n * HID + k] = h;
        outLo[(size_t)n * HID + k] = __float2bfloat16(x - __bfloat162float(h));
    }
}

// ---------------------------------------------------------------------------
// bf16x3 HMMA GEMM with 3-stage cp.async pipeline.
// CTA tile 128x128, BK=32 bf16, 256 threads (8 warps 2x4), 64x32 warp tile.
// SRC 0: QKV (epilogue bias -> bf16 hi/lo q/k/v scatter).
// SRC 1: proj (A = g_chi/g_clo, epilogue -> fp32 out).
// ---------------------------------------------------------------------------
#define O_AH 0
#define O_AL 8192
#define O_BH 16384
#define O_BL 24576
#define STAGE_B 32768
#define NSTAGE 3
#define GEMM_DSMEM (NSTAGE * STAGE_B)   // 98304

__device__ __forceinline__ uint32_t swz_off(int row, int unit) {
    return (uint32_t)(row * 64 + ((unit ^ ((row >> 1) & 3)) << 4));
}

template<int NDIM, int SRC>
__global__ __launch_bounds__(256, 2) void gemm_hmma_kernel(
    const float* __restrict__ bias, float* __restrict__ out)
{
    extern __shared__ char smem[];
    const uint32_t sbase = smem_u32(smem);

    const int tid  = threadIdx.x;
    const int lane = tid & 31;
    const int wid  = tid >> 5;
    const int wRow = wid >> 2;
    const int wCol = wid & 3;
    const int rowBase = blockIdx.y * 128;
    const int colBase = blockIdx.x * 128;

    const __nv_bfloat16* Ahi = (SRC == 0) ? g_ahi : g_chi;
    const __nv_bfloat16* Alo = (SRC == 0) ? g_alo : g_clo;
    const __nv_bfloat16* Bhi = (SRC == 0) ? g_wqh : g_wph;
    const __nv_bfloat16* Blo = (SRC == 0) ? g_wql : g_wpl;

    float c[4][4][4];
#pragma unroll
    for (int i = 0; i < 4; i++)
#pragma unroll
        for (int j = 0; j < 4; j++)
#pragma unroll
            for (int e = 0; e < 4; e++) c[i][j][e] = 0.0f;

    // gmem->smem geometry: 512 16B-units/tile; thread handles units tid, tid+256
    int uRow[2], uUnit[2];
    uint32_t uSwz[2];
    size_t aOff0[2], bOff0[2];
#pragma unroll
    for (int i = 0; i < 2; i++) {
        int u = tid + i * 256;
        uRow[i]  = u >> 2;
        uUnit[i] = u & 3;
        uSwz[i]  = swz_off(uRow[i], uUnit[i]);
        aOff0[i] = (size_t)(rowBase + uRow[i]) * HID + uUnit[i] * 8;
        bOff0[i] = (size_t)(colBase + uRow[i]) * HID + uUnit[i] * 8;
    }

    const int aRowLane  = lane & 15;
    const int aUnitSel  = lane >> 4;
    const int bRowLane  = (lane & 7) + ((lane >> 4) & 1) * 8;
    const int bUnitSel  = (lane >> 3) & 1;

    uint32_t aAddrBase[4], bAddrBase[2];
    int aMask[4], bMask[2];
#pragma unroll
    for (int i = 0; i < 4; i++) {
        int r = wRow * 64 + i * 16 + aRowLane;
        aMask[i] = (r >> 1) & 3;
        aAddrBase[i] = (uint32_t)(r * 64);
    }
#pragma unroll
    for (int j2 = 0; j2 < 2; j2++) {
        int r = wCol * 32 + j2 * 16 + bRowLane;
        bMask[j2] = (r >> 1) & 3;
        bAddrBase[j2] = (uint32_t)(r * 64);
    }

    const int NIT = HID / 32;   // 64

    // prologue: issue stages 0, 1
#pragma unroll
    for (int s = 0; s < NSTAGE - 1; s++) {
        const int k0 = s * 32;
        const uint32_t sp = sbase + s * STAGE_B;
#pragma unroll
        for (int i = 0; i < 2; i++) {
            cp16(sp + O_AH + uSwz[i], Ahi + aOff0[i] + k0);
            cp16(sp + O_AL + uSwz[i], Alo + aOff0[i] + k0);
            cp16(sp + O_BH + uSwz[i], Bhi + bOff0[i] + k0);
            cp16(sp + O_BL + uSwz[i], Blo + bOff0[i] + k0);
        }
        CP_COMMIT();
    }

    int buf = 0;
    for (int it = 0; it < NIT; ++it) {
        CP_WAIT(NSTAGE - 2);
        __syncthreads();

        // issue loads for stage it+2 (into the buffer freed at it-1)
        if (it + NSTAGE - 1 < NIT) {
            const int k0 = (it + NSTAGE - 1) * 32;
            const uint32_t sp = sbase + ((it + NSTAGE - 1) % NSTAGE) * STAGE_B;
#pragma unroll
            for (int i = 0; i < 2; i++) {
                cp16(sp + O_AH + uSwz[i], Ahi + aOff0[i] + k0);
                cp16(sp + O_AL + uSwz[i], Alo + aOff0[i] + k0);
                cp16(sp + O_BH + uSwz[i], Bhi + bOff0[i] + k0);
                cp16(sp + O_BL + uSwz[i], Blo + bOff0[i] + k0);
            }
        }
        CP_COMMIT();   // commit every iter (possibly empty) keeps group count aligned

        const uint32_t sp = sbase + buf * STAGE_B;
#pragma unroll
        for (int ks = 0; ks < 2; ks++) {
            uint32_t Ah[4][4], Al[4][4], Bh[2][4], Bl[2][4];
#pragma unroll
            for (int i = 0; i < 4; i++) {
                uint32_t off = aAddrBase[i] +
                    (uint32_t)(((ks * 2 + aUnitSel) ^ aMask[i]) << 4);
                ldmx4(Ah[i], sp + O_AH + off);
                ldmx4(Al[i], sp + O_AL + off);
            }
#pragma unroll
            for (int j2 = 0; j2 < 2; j2++) {
                uint32_t off = bAddrBase[j2] +
                    (uint32_t)(((ks * 2 + bUnitSel) ^ bMask[j2]) << 4);
                ldmx4(Bh[j2], sp + O_BH + off);
                ldmx4(Bl[j2], sp + O_BL + off);
            }
#pragma unroll
            for (int i = 0; i < 4; i++)
#pragma unroll
                for (int j = 0; j < 4; j++) {
                    const int g = j >> 1, p = (j & 1) * 2;
                    mma_bf16(c[i][j], Ah[i][0], Ah[i][1], Ah[i][2], Ah[i][3],
                             Bh[g][p], Bh[g][p + 1]);
                    mma_bf16(c[i][j], Ah[i][0], Ah[i][1], Ah[i][2], Ah[i][3],
                             Bl[g][p], Bl[g][p + 1]);
                    mma_bf16(c[i][j], Al[i][0], Al[i][1], Al[i][2], Al[i][3],
                             Bh[g][p], Bh[g][p + 1]);
                }
        }
        buf = (buf + 1 == NSTAGE) ? 0 : buf + 1;
    }

    const int lq = lane >> 2;
    const int lr = lane & 3;
#pragma unroll
    for (int i = 0; i < 4; i++) {
        const int r0 = rowBase + wRow * 64 + i * 16 + lq;
#pragma unroll
        for (int j = 0; j < 4; j++) {
            const int cc = colBase + wCol * 32 + j * 8 + 2 * lr;
            if (SRC == 0) {
#pragma unroll
                for (int e = 0; e < 4; e++) {
                    const int r = r0 + (e >> 1) * 8;
                    const int col = cc + (e & 1);
                    const float v = c[i][j][e] + bias[col];
                    const int s = r >> 1;       // BATCH == 2
                    const int b = r & 1;
                    const int h = col / 384;
                    const int jj = col - h * 384;
                    const int which = jj >> 7;  // 0=q, 1=k, 2=v
                    const int dd = jj & 127;
                    __nv_bfloat16* ph = (which == 0) ? g_qh : (which == 1 ? g_kh : g_vh);
                    __nv_bfloat16* pl = (which == 0) ? g_ql : (which == 1 ? g_kl : g_vl);
                    const size_t idx = (size_t)(((b * NH + h) * S_LEN) + s) * HD + dd;
                    __nv_bfloat16 hh = __float2bfloat16(v);
                    ph[idx] = hh;
                    pl[idx] = __float2bfloat16(v - __bfloat162float(hh));
                }
            } else {
                float2 v0 = make_float2(c[i][j][0], c[i][j][1]);
                float2 v1 = make_float2(c[i][j][2], c[i][j][3]);
                *(float2*)(out + (size_t)r0 * NDIM + cc) = v0;
                *(float2*)(out + (size_t)(r0 + 8) * NDIM + cc) = v1;
            }
        }
    }
}

// ---------------------------------------------------------------------------
// MMA flash attention (validated R7). Block = (b,h,64-row q tile), 4 warps.
// ---------------------------------------------------------------------------
#define ATQ 64
#define NQT (S_LEN / ATQ)        // 32
#define A_SMEM (6 * 16384)
#define SQ_H 0
#define SQ_L 16384
#define SK_H 32768
#define SK_L 49152
#define SV_H 65536
#define SV_L 81920

__device__ __forceinline__ uint32_t soff(int row, int unit) {
    return (uint32_t)(row * 256 + ((unit ^ (row & 7)) << 4));
}

__global__ __launch_bounds__(128) void attn_mma_kernel(
    const unsigned char* __restrict__ mask)
{
    extern __shared__ char sm8[];
    const uint32_t sb = smem_u32(sm8);

    const int bid = blockIdx.x;
    const int qt = NQT - 1 - (bid % NQT);
    const int bh = bid / NQT;
    const int b = bh / NH;
    const int h = bh % NH;
    const int q0 = qt * ATQ;

    const int tid = threadIdx.x;
    const int lane = tid & 31;
    const int w = tid >> 5;
    const int lq = lane >> 2;
    const int lr = lane & 3;
    const float inv_norm = 0.08838834764831845f;

    {
        const __nv_bfloat16* Qh = g_qh + ((size_t)bh * S_LEN + q0) * HD;
        const __nv_bfloat16* Ql = g_ql + ((size_t)bh * S_LEN + q0) * HD;
#pragma unroll
        for (int i = 0; i < 8; i++) {
            int u = tid + i * 128;
            int row = u >> 4, un = u & 15;
            uint32_t off = soff(row, un);
            *(uint4*)(sm8 + SQ_H + off) = ((const uint4*)(Qh + row * HD))[un];
            *(uint4*)(sm8 + SQ_L + off) = ((const uint4*)(Ql + row * HD))[un];
        }
    }

    const int sg0 = q0 + w * 16 + lq;
    const int sg1 = sg0 + 8;
    const unsigned char* mrow0 = mask + ((size_t)b * S_LEN + sg0) * S_LEN;
    const unsigned char* mrow1 = mask + ((size_t)b * S_LEN + sg1) * S_LEN;

    float m0 = -1e30f, m1 = -1e30f, l0 = 0.0f, l1 = 0.0f;
    float o[16][4];
#pragma unroll
    for (int jd = 0; jd < 16; jd++)
#pragma unroll
        for (int e = 0; e < 4; e++) o[jd][e] = 0.0f;

    for (int kt = 0; kt <= qt; ++kt) {
        const int k0 = kt * ATQ;
        __syncthreads();
        {
            const __nv_bfloat16* Kh = g_kh + ((size_t)bh * S_LEN + k0) * HD;
            const __nv_bfloat16* Kl = g_kl + ((size_t)bh * S_LEN + k0) * HD;
            const __nv_bfloat16* Vh = g_vh + ((size_t)bh * S_LEN + k0) * HD;
            const __nv_bfloat16* Vl = g_vl + ((size_t)bh * S_LEN + k0) * HD;
#pragma unroll
            for (int i = 0; i < 8; i++) {
                int u = tid + i * 128;
                int row = u >> 4, un = u & 15;
                uint32_t off = soff(row, un);
                *(uint4*)(sm8 + SK_H + off) = ((const uint4*)(Kh + row * HD))[un];
                *(uint4*)(sm8 + SK_L + off) = ((const uint4*)(Kl + row * HD))[un];
                *(uint4*)(sm8 + SV_H + off) = ((const uint4*)(Vh + row * HD))[un];
                *(uint4*)(sm8 + SV_L + off) = ((const uint4*)(Vl + row * HD))[un];
            }
        }
        __syncthreads();

        float c[8][4];
#pragma unroll
        for (int j = 0; j < 8; j++)
#pragma unroll
            for (int e = 0; e < 4; e++) c[j][e] = 0.0f;

#pragma unroll
        for (int ks = 0; ks < 8; ks++) {
            uint32_t qh4[4], ql4[4];
            {
                int r = w * 16 + (lane & 15);
                int un = ks * 2 + (lane >> 4);
                uint32_t off = soff(r, un);
                ldmx4(qh4, sb + SQ_H + off);
                ldmx4(ql4, sb + SQ_L + off);
            }
#pragma unroll
            for (int nt = 0; nt < 4; nt++) {
                int r = nt * 16 + (lane & 7) + ((lane >> 4) & 1) * 8;
                int un = ks * 2 + ((lane >> 3) & 1);
                uint32_t off = soff(r, un);
                uint32_t kh4[4], kl4[4];
                ldmx4(kh4, sb + SK_H + off);
                ldmx4(kl4, sb + SK_L + off);
                mma_bf16(c[2 * nt], qh4[0], qh4[1], qh4[2], qh4[3], kh4[0], kh4[1]);
                mma_bf16(c[2 * nt], qh4[0], qh4[1], qh4[2], qh4[3], kl4[0], kl4[1]);
                mma_bf16(c[2 * nt], ql4[0], ql4[1], ql4[2], ql4[3], kh4[0], kh4[1]);
                mma_bf16(c[2 * nt + 1], qh4[0], qh4[1], qh4[2], qh4[3], kh4[2], kh4[3]);
                mma_bf16(c[2 * nt + 1], qh4[0], qh4[1], qh4[2], qh4[3], kl4[2], kl4[3]);
                mma_bf16(c[2 * nt + 1], ql4[0], ql4[1], ql4[2], ql4[3], kh4[2], kh4[3]);
            }
        }

#pragma unroll
        for (int j = 0; j < 8; j++) {
            const int t0 = k0 + j * 8 + 2 * lr;
            uchar2 mb0 = *(const uchar2*)(mrow0 + t0);
            uchar2 mb1 = *(const uchar2*)(mrow1 + t0);
            c[j][0] = (t0 > sg0     || mb0.x) ? -10000.0f : c[j][0] * inv_norm;
            c[j][1] = (t0 + 1 > sg0 || mb0.y) ? -10000.0f : c[j][1] * inv_norm;
            c[j][2] = (t0 > sg1     || mb1.x) ? -10000.0f : c[j][2] * inv_norm;
            c[j][3] = (t0 + 1 > sg1 || mb1.y) ? -10000.0f : c[j][3] * inv_norm;
        }

        float vm0 = -1e30f, vm1 = -1e30f;
#pragma unroll
        for (int j = 0; j < 8; j++) {
            vm0 = fmaxf(vm0, fmaxf(c[j][0], c[j][1]));
            vm1 = fmaxf(vm1, fmaxf(c[j][2], c[j][3]));
        }
        vm0 = fmaxf(vm0, __shfl_xor_sync(0xffffffffu, vm0, 1));
        vm0 = fmaxf(vm0, __shfl_xor_sync(0xffffffffu, vm0, 2));
        vm1 = fmaxf(vm1, __shfl_xor_sync(0xffffffffu, vm1, 1));
        vm1 = fmaxf(vm1, __shfl_xor_sync(0xffffffffu, vm1, 2));
        const float mn0 = fmaxf(m0, vm0), mn1 = fmaxf(m1, vm1);
        const float cor0 = __expf(m0 - mn0), cor1 = __expf(m1 - mn1);
        m0 = mn0; m1 = mn1;

        uint32_t aPh[8][2], aPl[8][2];
        float ls0 = 0.0f, ls1 = 0.0f;
#pragma unroll
        for (int j = 0; j < 8; j++) {
            float p0 = __expf(c[j][0] - mn0);
            float p1 = __expf(c[j][1] - mn0);
            float p2 = __expf(c[j][2] - mn1);
            float p3 = __expf(c[j][3] - mn1);
            ls0 += p0 + p1; ls1 += p2 + p3;
            __nv_bfloat162 h01 = __floats2bfloat162_rn(p0, p1);
            __nv_bfloat162 h23 = __floats2bfloat162_rn(p2, p3);
            __nv_bfloat162 l01 = __floats2bfloat162_rn(
                p0 - __bfloat162float(h01.x), p1 - __bfloat162float(h01.y));
            __nv_bfloat162 l23 = __floats2bfloat162_rn(
                p2 - __bfloat162float(h23.x), p3 - __bfloat162float(h23.y));
            aPh[j][0] = *(uint32_t*)&h01;
            aPh[j][1] = *(uint32_t*)&h23;
            aPl[j][0] = *(uint32_t*)&l01;
            aPl[j][1] = *(uint32_t*)&l23;
        }
        l0 = l0 * cor0 + ls0;
        l1 = l1 * cor1 + ls1;
#pragma unroll
        for (int jd = 0; jd < 16; jd++) {
            o[jd][0] *= cor0; o[jd][1] *= cor0;
            o[jd][2] *= cor1; o[jd][3] *= cor1;
        }

#pragma unroll
        for (int ss = 0; ss < 4; ss++) {
            const uint32_t ah0 = aPh[2 * ss][0], ah1 = aPh[2 * ss][1];
            const uint32_t ah2 = aPh[2 * ss + 1][0], ah3 = aPh[2 * ss + 1][1];
            const uint32_t al0 = aPl[2 * ss][0], al1 = aPl[2 * ss][1];
            const uint32_t al2 = aPl[2 * ss + 1][0], al3 = aPl[2 * ss + 1][1];
            int r = ss * 16 + (lane & 7) + ((lane >> 3) & 1) * 8;
#pragma unroll
            for (int dt = 0; dt < 8; dt++) {
                int un = dt * 2 + ((lane >> 4) & 1);
                uint32_t off = soff(r, un);
                uint32_t vh4[4], vl4[4];
                ldmx4t(vh4, sb + SV_H + off);
                ldmx4t(vl4, sb + SV_L + off);
                mma_bf16(o[2 * dt], ah0, ah1, ah2, ah3, vh4[0], vh4[1]);
                mma_bf16(o[2 * dt], ah0, ah1, ah2, ah3, vl4[0], vl4[1]);
                mma_bf16(o[2 * dt], al0, al1, al2, al3, vh4[0], vh4[1]);
                mma_bf16(o[2 * dt + 1], ah0, ah1, ah2, ah3, vh4[2], vh4[3]);
                mma_bf16(o[2 * dt + 1], ah0, ah1, ah2, ah3, vl4[2], vl4[3]);
                mma_bf16(o[2 * dt + 1], al0, al1, al2, al3, vh4[2], vh4[3]);
            }
        }
    }

    l0 += __shfl_xor_sync(0xffffffffu, l0, 1);
    l0 += __shfl_xor_sync(0xffffffffu, l0, 2);
    l1 += __shfl_xor_sync(0xffffffffu, l1, 1);
    l1 += __shfl_xor_sync(0xffffffffu, l1, 2);
    const float inv0 = 1.0f / l0, inv1 = 1.0f / l1;

    __nv_bfloat16* chiBase = g_chi + (size_t)h * HD;
    __nv_bfloat16* cloBase = g_clo + (size_t)h * HD;
    const size_t row0 = (size_t)(sg0 * BATCH + b) * HID;
    const size_t row1 = (size_t)(sg1 * BATCH + b) * HID;
#pragma unroll
    for (int jd = 0; jd < 16; jd++) {
        const int d = jd * 8 + 2 * lr;
        float v0 = o[jd][0] * inv0, v1 = o[jd][1] * inv0;
        float v2 = o[jd][2] * inv1, v3 = o[jd][3] * inv1;
        __nv_bfloat162 h01 = __floats2bfloat162_rn(v0, v1);
        __nv_bfloat162 l01 = __floats2bfloat162_rn(
            v0 - __bfloat162float(h01.x), v1 - __bfloat162float(h01.y));
        __nv_bfloat162 h23 = __floats2bfloat162_rn(v2, v3);
        __nv_bfloat162 l23 = __floats2bfloat162_rn(
            v2 - __bfloat162float(h23.x), v3 - __bfloat162float(h23.y));
        *(__nv_bfloat162*)(chiBase + row0 + d) = h01;
        *(__nv_bfloat162*)(cloBase + row0 + d) = l01;
        *(__nv_bfloat162*)(chiBase + row1 + d) = h23;
        *(__nv_bfloat162*)(cloBase + row1 + d) = l23;
    }
}

__global__ void copy_bias_kernel(const float* __restrict__ bias, float* __restrict__ dst)
{
    int i = blockIdx.x * blockDim.x + threadIdx.x;
    if (i < HID) dst[i] = bias[i];
}

// ---------------------------------------------------------------------------
extern "C" void kernel_launch(void* const* d_in, const int* in_sizes, int n_in,
                              void* d_out, int out_size)
{
    const float* hidden   = (const float*)d_in[0];
    const unsigned char* mask = (const unsigned char*)d_in[1];
    const float* qkv_w    = (const float*)d_in[2];
    const float* qkv_b    = (const float*)d_in[3];
    const float* proj_w   = (const float*)d_in[4];
    const float* proj_b   = (const float*)d_in[5];
    float* out = (float*)d_out;

    cudaFuncSetAttribute(attn_mma_kernel,
                         cudaFuncAttributeMaxDynamicSharedMemorySize, A_SMEM);
    cudaFuncSetAttribute(gemm_hmma_kernel<N3H, 0>,
                         cudaFuncAttributeMaxDynamicSharedMemorySize, GEMM_DSMEM);
    cudaFuncSetAttribute(gemm_hmma_kernel<HID, 1>,
                         cudaFuncAttributeMaxDynamicSharedMemorySize, GEMM_DSMEM);

    // 1. prep splits
    split_hidden_kernel<<<M_ROWS * HID / 256, 256>>>(hidden);
    transpose_split_kernel<N3H, 0><<<dim3(N3H / 32, HID / 32), dim3(32, 8)>>>(qkv_w);
    transpose_split_kernel<HID, 1><<<dim3(HID / 32, HID / 32), dim3(32, 8)>>>(proj_w);

    // 2. QKV GEMM -> bf16 hi/lo q/k/v
    gemm_hmma_kernel<N3H, 0><<<dim3(N3H / 128, M_ROWS / 128), 256, GEMM_DSMEM>>>(qkv_b, nullptr);

    // 3. MMA flash attention -> bf16 hi/lo ctx
    attn_mma_kernel<<<NBH * NQT, 128, A_SMEM>>>(mask);

    // 4. proj GEMM -> out
    gemm_hmma_kernel<HID, 1><<<dim3(HID / 128, M_ROWS / 128), 256, GEMM_DSMEM>>>(nullptr, out);

    if (out_size > M_ROWS * HID) {
        copy_bias_kernel<<<(HID + 255) / 256, 256>>>(proj_b, out + (size_t)M_ROWS * HID);
    }
}

// round 12
// speedup vs baseline: 4.7848x; 1.0106x over previous
#include <cuda_runtime.h>
#include <cuda_bf16.h>
#include <math.h>
#include <stdint.h>

#define S_LEN 2048
#define BATCH 2
#define HID   2048
#define NH    16
#define HD    128
#define M_ROWS (S_LEN * BATCH)   // 4096
#define N3H    (3 * HID)         // 6144
#define NBH    (BATCH * NH)      // 32

// ---------------------------------------------------------------------------
// Device-global scratch (allocation-free). All attention operands bf16 hi/lo.
// ---------------------------------------------------------------------------
__device__ __nv_bfloat16 g_qh[NBH * S_LEN * HD];
__device__ __nv_bfloat16 g_ql[NBH * S_LEN * HD];
__device__ __nv_bfloat16 g_kh[NBH * S_LEN * HD];
__device__ __nv_bfloat16 g_kl[NBH * S_LEN * HD];
__device__ __nv_bfloat16 g_vh[NBH * S_LEN * HD];
__device__ __nv_bfloat16 g_vl[NBH * S_LEN * HD];
__device__ __nv_bfloat16 g_chi[M_ROWS * HID];
__device__ __nv_bfloat16 g_clo[M_ROWS * HID];

__device__ __nv_bfloat16 g_ahi[M_ROWS * HID];       // hidden split
__device__ __nv_bfloat16 g_alo[M_ROWS * HID];
__device__ __nv_bfloat16 g_wqh[(size_t)N3H * HID];  // qkv_w^T split
__device__ __nv_bfloat16 g_wql[(size_t)N3H * HID];
__device__ __nv_bfloat16 g_wph[(size_t)HID * HID];  // proj_w^T split
__device__ __nv_bfloat16 g_wpl[(size_t)HID * HID];

// ---------------------------------------------------------------------------
// MMA / ldmatrix / cp.async helpers
// ---------------------------------------------------------------------------
__device__ __forceinline__ uint32_t smem_u32(const void* p) {
    uint32_t a;
    asm("{ .reg .u64 t; cvta.to.shared.u64 t, %1; cvt.u32.u64 %0, t; }"
        : "=r"(a) : "l"(p));
    return a;
}
__device__ __forceinline__ void ldmx4(uint32_t r[4], uint32_t addr) {
    asm volatile("ldmatrix.sync.aligned.m8n8.x4.shared.b16 {%0,%1,%2,%3}, [%4];"
                 : "=r"(r[0]), "=r"(r[1]), "=r"(r[2]), "=r"(r[3]) : "r"(addr));
}
__device__ __forceinline__ void ldmx4t(uint32_t r[4], uint32_t addr) {
    asm volatile("ldmatrix.sync.aligned.m8n8.x4.trans.shared.b16 {%0,%1,%2,%3}, [%4];"
                 : "=r"(r[0]), "=r"(r[1]), "=r"(r[2]), "=r"(r[3]) : "r"(addr));
}
__device__ __forceinline__ void mma_bf16(float c[4],
                                         uint32_t a0, uint32_t a1, uint32_t a2, uint32_t a3,
                                         uint32_t b0, uint32_t b1) {
    asm volatile(
        "mma.sync.aligned.m16n8k16.row.col.f32.bf16.bf16.f32 "
        "{%0,%1,%2,%3}, {%4,%5,%6,%7}, {%8,%9}, {%0,%1,%2,%3};"
        : "+f"(c[0]), "+f"(c[1]), "+f"(c[2]), "+f"(c[3])
        : "r"(a0), "r"(a1), "r"(a2), "r"(a3), "r"(b0), "r"(b1));
}
__device__ __forceinline__ void cp16(uint32_t saddr, const void* g) {
    asm volatile("cp.async.cg.shared.global [%0], [%1], 16;" :: "r"(saddr), "l"(g));
}
#define CP_COMMIT() asm volatile("cp.async.commit_group;" ::: "memory")
#define CP_WAIT(n)  asm volatile("cp.async.wait_group %0;" :: "n"(n) : "memory")

// ---------------------------------------------------------------------------
// Split prep kernels
// ---------------------------------------------------------------------------
__global__ void split_hidden_kernel(const float* __restrict__ in)
{
    int i = blockIdx.x * blockDim.x + threadIdx.x;
    float x = in[i];
    __nv_bfloat16 h = __float2bfloat16(x);
    g_ahi[i] = h;
    g_alo[i] = __float2bfloat16(x - __bfloat162float(h));
}

template<int NIN, int WSEL>
__global__ void transpose_split_kernel(const float* __restrict__ W)
{
    __shared__ float s[32][33];
    const int tx = threadIdx.x, ty = threadIdx.y;
    const int n0 = blockIdx.x * 32, k0 = blockIdx.y * 32;
    __nv_bfloat16* outHi = (WSEL == 0) ? g_wqh : g_wph;
    __nv_bfloat16* outLo = (WSEL == 0) ? g_wql : g_wpl;
#pragma unroll
    for (int i = 0; i < 4; i++) {
        int k = k0 + ty + i * 8;
        s[ty + i * 8][tx] = W[(size_t)k * NIN + n0 + tx];
    }
    __syncthreads();
#pragma unroll
    for (int i = 0; i < 4; i++) {
        int n = n0 + ty + i * 8;
        int k = k0 + tx;
        float x = s[tx][ty + i * 8];
        __nv_bfloat16 h = __float2bfloat16(x);
        outHi[(size_t)n * HID + k] = h;
        outLo[(size_t)n * HID + k] = __float2bfloat16(x - __bfloat162float(h));
    }
}

// ---------------------------------------------------------------------------
// bf16x3 HMMA GEMM with 3-stage cp.async pipeline (validated R11).
// ---------------------------------------------------------------------------
#define O_AH 0
#define O_AL 8192
#define O_BH 16384
#define O_BL 24576
#define STAGE_B 32768
#define NSTAGE 3
#define GEMM_DSMEM (NSTAGE * STAGE_B)   // 98304

__device__ __forceinline__ uint32_t swz_off(int row, int unit) {
    return (uint32_t)(row * 64 + ((unit ^ ((row >> 1) & 3)) << 4));
}

template<int NDIM, int SRC>
__global__ __launch_bounds__(256, 2) void gemm_hmma_kernel(
    const float* __restrict__ bias, float* __restrict__ out)
{
    extern __shared__ char smem[];
    const uint32_t sbase = smem_u32(smem);

    const int tid  = threadIdx.x;
    const int lane = tid & 31;
    const int wid  = tid >> 5;
    const int wRow = wid >> 2;
    const int wCol = wid & 3;
    const int rowBase = blockIdx.y * 128;
    const int colBase = blockIdx.x * 128;

    const __nv_bfloat16* Ahi = (SRC == 0) ? g_ahi : g_chi;
    const __nv_bfloat16* Alo = (SRC == 0) ? g_alo : g_clo;
    const __nv_bfloat16* Bhi = (SRC == 0) ? g_wqh : g_wph;
    const __nv_bfloat16* Blo = (SRC == 0) ? g_wql : g_wpl;

    float c[4][4][4];
#pragma unroll
    for (int i = 0; i < 4; i++)
#pragma unroll
        for (int j = 0; j < 4; j++)
#pragma unroll
            for (int e = 0; e < 4; e++) c[i][j][e] = 0.0f;

    int uRow[2], uUnit[2];
    uint32_t uSwz[2];
    size_t aOff0[2], bOff0[2];
#pragma unroll
    for (int i = 0; i < 2; i++) {
        int u = tid + i * 256;
        uRow[i]  = u >> 2;
        uUnit[i] = u & 3;
        uSwz[i]  = swz_off(uRow[i], uUnit[i]);
        aOff0[i] = (size_t)(rowBase + uRow[i]) * HID + uUnit[i] * 8;
        bOff0[i] = (size_t)(colBase + uRow[i]) * HID + uUnit[i] * 8;
    }

    const int aRowLane  = lane & 15;
    const int aUnitSel  = lane >> 4;
    const int bRowLane  = (lane & 7) + ((lane >> 4) & 1) * 8;
    const int bUnitSel  = (lane >> 3) & 1;

    uint32_t aAddrBase[4], bAddrBase[2];
    int aMask[4], bMask[2];
#pragma unroll
    for (int i = 0; i < 4; i++) {
        int r = wRow * 64 + i * 16 + aRowLane;
        aMask[i] = (r >> 1) & 3;
        aAddrBase[i] = (uint32_t)(r * 64);
    }
#pragma unroll
    for (int j2 = 0; j2 < 2; j2++) {
        int r = wCol * 32 + j2 * 16 + bRowLane;
        bMask[j2] = (r >> 1) & 3;
        bAddrBase[j2] = (uint32_t)(r * 64);
    }

    const int NIT = HID / 32;   // 64

#pragma unroll
    for (int s = 0; s < NSTAGE - 1; s++) {
        const int k0 = s * 32;
        const uint32_t sp = sbase + s * STAGE_B;
#pragma unroll
        for (int i = 0; i < 2; i++) {
            cp16(sp + O_AH + uSwz[i], Ahi + aOff0[i] + k0);
            cp16(sp + O_AL + uSwz[i], Alo + aOff0[i] + k0);
            cp16(sp + O_BH + uSwz[i], Bhi + bOff0[i] + k0);
            cp16(sp + O_BL + uSwz[i], Blo + bOff0[i] + k0);
        }
        CP_COMMIT();
    }

    int buf = 0;
    for (int it = 0; it < NIT; ++it) {
        CP_WAIT(NSTAGE - 2);
        __syncthreads();

        if (it + NSTAGE - 1 < NIT) {
            const int k0 = (it + NSTAGE - 1) * 32;
            const uint32_t sp = sbase + ((it + NSTAGE - 1) % NSTAGE) * STAGE_B;
#pragma unroll
            for (int i = 0; i < 2; i++) {
                cp16(sp + O_AH + uSwz[i], Ahi + aOff0[i] + k0);
                cp16(sp + O_AL + uSwz[i], Alo + aOff0[i] + k0);
                cp16(sp + O_BH + uSwz[i], Bhi + bOff0[i] + k0);
                cp16(sp + O_BL + uSwz[i], Blo + bOff0[i] + k0);
            }
        }
        CP_COMMIT();

        const uint32_t sp = sbase + buf * STAGE_B;
#pragma unroll
        for (int ks = 0; ks < 2; ks++) {
            uint32_t Ah[4][4], Al[4][4], Bh[2][4], Bl[2][4];
#pragma unroll
            for (int i = 0; i < 4; i++) {
                uint32_t off = aAddrBase[i] +
                    (uint32_t)(((ks * 2 + aUnitSel) ^ aMask[i]) << 4);
                ldmx4(Ah[i], sp + O_AH + off);
                ldmx4(Al[i], sp + O_AL + off);
            }
#pragma unroll
            for (int j2 = 0; j2 < 2; j2++) {
                uint32_t off = bAddrBase[j2] +
                    (uint32_t)(((ks * 2 + bUnitSel) ^ bMask[j2]) << 4);
                ldmx4(Bh[j2], sp + O_BH + off);
                ldmx4(Bl[j2], sp + O_BL + off);
            }
#pragma unroll
            for (int i = 0; i < 4; i++)
#pragma unroll
                for (int j = 0; j < 4; j++) {
                    const int g = j >> 1, p = (j & 1) * 2;
                    mma_bf16(c[i][j], Ah[i][0], Ah[i][1], Ah[i][2], Ah[i][3],
                             Bh[g][p], Bh[g][p + 1]);
                    mma_bf16(c[i][j], Ah[i][0], Ah[i][1], Ah[i][2], Ah[i][3],
                             Bl[g][p], Bl[g][p + 1]);
                    mma_bf16(c[i][j], Al[i][0], Al[i][1], Al[i][2], Al[i][3],
                             Bh[g][p], Bh[g][p + 1]);
                }
        }
        buf = (buf + 1 == NSTAGE) ? 0 : buf + 1;
    }

    const int lq = lane >> 2;
    const int lr = lane & 3;
#pragma unroll
    for (int i = 0; i < 4; i++) {
        const int r0 = rowBase + wRow * 64 + i * 16 + lq;
#pragma unroll
        for (int j = 0; j < 4; j++) {
            const int cc = colBase + wCol * 32 + j * 8 + 2 * lr;
            if (SRC == 0) {
#pragma unroll
                for (int e = 0; e < 4; e++) {
                    const int r = r0 + (e >> 1) * 8;
                    const int col = cc + (e & 1);
                    const float v = c[i][j][e] + bias[col];
                    const int s = r >> 1;       // BATCH == 2
                    const int b = r & 1;
                    const int h = col / 384;
                    const int jj = col - h * 384;
                    const int which = jj >> 7;  // 0=q, 1=k, 2=v
                    const int dd = jj & 127;
                    __nv_bfloat16* ph = (which == 0) ? g_qh : (which == 1 ? g_kh : g_vh);
                    __nv_bfloat16* pl = (which == 0) ? g_ql : (which == 1 ? g_kl : g_vl);
                    const size_t idx = (size_t)(((b * NH + h) * S_LEN) + s) * HD + dd;
                    __nv_bfloat16 hh = __float2bfloat16(v);
                    ph[idx] = hh;
                    pl[idx] = __float2bfloat16(v - __bfloat162float(hh));
                }
            } else {
                float2 v0 = make_float2(c[i][j][0], c[i][j][1]);
                float2 v1 = make_float2(c[i][j][2], c[i][j][3]);
                *(float2*)(out + (size_t)r0 * NDIM + cc) = v0;
                *(float2*)(out + (size_t)(r0 + 8) * NDIM + cc) = v1;
            }
        }
    }
}

// ---------------------------------------------------------------------------
// MMA flash attention v2: 128-row Q tile, 256 threads (8 warps x 16 rows),
// double-buffered cp.async K/V, warp-uniform causal tile skip.
// ---------------------------------------------------------------------------
#define ATQ2 128
#define NQT2 (S_LEN / ATQ2)       // 16
#define SQ2_H 0
#define SQ2_L 32768
#define SKV0  65536               // stage base; stage stride 65536
#define KO_H  0
#define KO_L  16384
#define VO_H  32768
#define VO_L  49152
#define A2_SMEM (65536 + 2 * 65536)   // 196608

__device__ __forceinline__ uint32_t soff(int row, int unit) {
    return (uint32_t)(row * 256 + ((unit ^ (row & 7)) << 4));
}

__global__ __launch_bounds__(256, 1) void attn_mma_kernel(
    const unsigned char* __restrict__ mask)
{
    extern __shared__ char sm8[];
    const uint32_t sb = smem_u32(sm8);

    const int bid = blockIdx.x;
    const int qt = NQT2 - 1 - (bid % NQT2);   // heavy tiles first
    const int bh = bid / NQT2;
    const int b = bh / NH;
    const int h = bh % NH;
    const int q0 = qt * ATQ2;
    const int NKT = 2 * qt + 2;               // 64-key tiles covering [0, q0+128)

    const int tid = threadIdx.x;
    const int lane = tid & 31;
    const int w = tid >> 5;                   // warp 0..7 -> rows w*16..w*16+15
    const int lq = lane >> 2;
    const int lr = lane & 3;
    const float inv_norm = 0.08838834764831845f;

    const __nv_bfloat16* KhB = g_kh + (size_t)bh * S_LEN * HD;
    const __nv_bfloat16* KlB = g_kl + (size_t)bh * S_LEN * HD;
    const __nv_bfloat16* VhB = g_vh + (size_t)bh * S_LEN * HD;
    const __nv_bfloat16* VlB = g_vl + (size_t)bh * S_LEN * HD;

    // per-thread cp.async geometry for one 64x128 bf16 tile (16KB): 16 units/thr/4arr
    int cRow[4], cUn[4];
    uint32_t cSwz[4];
#pragma unroll
    for (int i = 0; i < 4; i++) {
        int u = tid + i * 256;
        cRow[i] = u >> 4;
        cUn[i]  = u & 15;
        cSwz[i] = soff(cRow[i], cUn[i]);
    }

    // issue stage 0 (kt = 0)
    {
        const uint32_t sp = sb + SKV0;
#pragma unroll
        for (int i = 0; i < 4; i++) {
            const size_t g = (size_t)cRow[i] * HD + cUn[i] * 8;
            cp16(sp + KO_H + cSwz[i], KhB + g);
            cp16(sp + KO_L + cSwz[i], KlB + g);
            cp16(sp + VO_H + cSwz[i], VhB + g);
            cp16(sp + VO_L + cSwz[i], VlB + g);
        }
        CP_COMMIT();
    }

    // load Q tile (plain loads; overlaps with stage-0 cp.async)
    {
        const __nv_bfloat16* Qh = g_qh + ((size_t)bh * S_LEN + q0) * HD;
        const __nv_bfloat16* Ql = g_ql + ((size_t)bh * S_LEN + q0) * HD;
#pragma unroll
        for (int i = 0; i < 8; i++) {
            int u = tid + i * 256;
            int row = u >> 4, un = u & 15;
            uint32_t off = soff(row, un);
            *(uint4*)(sm8 + SQ2_H + off) = ((const uint4*)(Qh + row * HD))[un];
            *(uint4*)(sm8 + SQ2_L + off) = ((const uint4*)(Ql + row * HD))[un];
        }
    }

    const int sg0 = q0 + w * 16 + lq;
    const int sg1 = sg0 + 8;
    const int wRowMax = q0 + w * 16 + 15;
    const unsigned char* mrow0 = mask + ((size_t)b * S_LEN + sg0) * S_LEN;
    const unsigned char* mrow1 = mask + ((size_t)b * S_LEN + sg1) * S_LEN;

    float m0 = -1e30f, m1 = -1e30f, l0 = 0.0f, l1 = 0.0f;
    float o[16][4];
#pragma unroll
    for (int jd = 0; jd < 16; jd++)
#pragma unroll
        for (int e = 0; e < 4; e++) o[jd][e] = 0.0f;

    for (int kt = 0; kt < NKT; ++kt) {
        __syncthreads();   // all warps done reading buffer (kt-1)&1 before refill

        // issue loads for kt+1 into buffer (kt+1)&1
        if (kt + 1 < NKT) {
            const uint32_t sp = sb + SKV0 + ((kt + 1) & 1) * 65536;
            const size_t kbase = (size_t)(kt + 1) * 64 * HD;
#pragma unroll
            for (int i = 0; i < 4; i++) {
                const size_t g = kbase + (size_t)cRow[i] * HD + cUn[i] * 8;
                cp16(sp + KO_H + cSwz[i], KhB + g);
                cp16(sp + KO_L + cSwz[i], KlB + g);
                cp16(sp + VO_H + cSwz[i], VhB + g);
                cp16(sp + VO_L + cSwz[i], VlB + g);
            }
            CP_COMMIT();
            CP_WAIT(1);
        } else {
            CP_WAIT(0);
        }
        __syncthreads();   // kt's data visible to all warps

        const int k0 = kt * 64;
        if (k0 <= wRowMax) {   // warp-uniform causal skip
            const uint32_t kb = sb + SKV0 + (kt & 1) * 65536;

            float c[8][4];
#pragma unroll
            for (int j = 0; j < 8; j++)
#pragma unroll
                for (int e = 0; e < 4; e++) c[j][e] = 0.0f;

#pragma unroll
            for (int ks = 0; ks < 8; ks++) {
                uint32_t qh4[4], ql4[4];
                {
                    int r = w * 16 + (lane & 15);
                    int un = ks * 2 + (lane >> 4);
                    uint32_t off = soff(r, un);
                    ldmx4(qh4, sb + SQ2_H + off);
                    ldmx4(ql4, sb + SQ2_L + off);
                }
#pragma unroll
                for (int nt = 0; nt < 4; nt++) {
                    int r = nt * 16 + (lane & 7) + ((lane >> 4) & 1) * 8;
                    int un = ks * 2 + ((lane >> 3) & 1);
                    uint32_t off = soff(r, un);
                    uint32_t kh4[4], kl4[4];
                    ldmx4(kh4, kb + KO_H + off);
                    ldmx4(kl4, kb + KO_L + off);
                    mma_bf16(c[2 * nt], qh4[0], qh4[1], qh4[2], qh4[3], kh4[0], kh4[1]);
                    mma_bf16(c[2 * nt], qh4[0], qh4[1], qh4[2], qh4[3], kl4[0], kl4[1]);
                    mma_bf16(c[2 * nt], ql4[0], ql4[1], ql4[2], ql4[3], kh4[0], kh4[1]);
                    mma_bf16(c[2 * nt + 1], qh4[0], qh4[1], qh4[2], qh4[3], kh4[2], kh4[3]);
                    mma_bf16(c[2 * nt + 1], qh4[0], qh4[1], qh4[2], qh4[3], kl4[2], kl4[3]);
                    mma_bf16(c[2 * nt + 1], ql4[0], ql4[1], ql4[2], ql4[3], kh4[2], kh4[3]);
                }
            }

#pragma unroll
            for (int j = 0; j < 8; j++) {
                const int t0 = k0 + j * 8 + 2 * lr;
                uchar2 mb0 = *(const uchar2*)(mrow0 + t0);
                uchar2 mb1 = *(const uchar2*)(mrow1 + t0);
                c[j][0] = (t0 > sg0     || mb0.x) ? -10000.0f : c[j][0] * inv_norm;
                c[j][1] = (t0 + 1 > sg0 || mb0.y) ? -10000.0f : c[j][1] * inv_norm;
                c[j][2] = (t0 > sg1     || mb1.x) ? -10000.0f : c[j][2] * inv_norm;
                c[j][3] = (t0 + 1 > sg1 || mb1.y) ? -10000.0f : c[j][3] * inv_norm;
            }

            float vm0 = -1e30f, vm1 = -1e30f;
#pragma unroll
            for (int j = 0; j < 8; j++) {
                vm0 = fmaxf(vm0, fmaxf(c[j][0], c[j][1]));
                vm1 = fmaxf(vm1, fmaxf(c[j][2], c[j][3]));
            }
            vm0 = fmaxf(vm0, __shfl_xor_sync(0xffffffffu, vm0, 1));
            vm0 = fmaxf(vm0, __shfl_xor_sync(0xffffffffu, vm0, 2));
            vm1 = fmaxf(vm1, __shfl_xor_sync(0xffffffffu, vm1, 1));
            vm1 = fmaxf(vm1, __shfl_xor_sync(0xffffffffu, vm1, 2));
            const float mn0 = fmaxf(m0, vm0), mn1 = fmaxf(m1, vm1);
            const float cor0 = __expf(m0 - mn0), cor1 = __expf(m1 - mn1);
            m0 = mn0; m1 = mn1;

            uint32_t aPh[8][2], aPl[8][2];
            float ls0 = 0.0f, ls1 = 0.0f;
#pragma unroll
            for (int j = 0; j < 8; j++) {
                float p0 = __expf(c[j][0] - mn0);
                float p1 = __expf(c[j][1] - mn0);
                float p2 = __expf(c[j][2] - mn1);
                float p3 = __expf(c[j][3] - mn1);
                ls0 += p0 + p1; ls1 += p2 + p3;
                __nv_bfloat162 h01 = __floats2bfloat162_rn(p0, p1);
                __nv_bfloat162 h23 = __floats2bfloat162_rn(p2, p3);
                __nv_bfloat162 l01 = __floats2bfloat162_rn(
                    p0 - __bfloat162float(h01.x), p1 - __bfloat162float(h01.y));
                __nv_bfloat162 l23 = __floats2bfloat162_rn(
                    p2 - __bfloat162float(h23.x), p3 - __bfloat162float(h23.y));
                aPh[j][0] = *(uint32_t*)&h01;
                aPh[j][1] = *(uint32_t*)&h23;
                aPl[j][0] = *(uint32_t*)&l01;
                aPl[j][1] = *(uint32_t*)&l23;
            }
            l0 = l0 * cor0 + ls0;
            l1 = l1 * cor1 + ls1;
#pragma unroll
            for (int jd = 0; jd < 16; jd++) {
                o[jd][0] *= cor0; o[jd][1] *= cor0;
                o[jd][2] *= cor1; o[jd][3] *= cor1;
            }

#pragma unroll
            for (int ss = 0; ss < 4; ss++) {
                const uint32_t ah0 = aPh[2 * ss][0], ah1 = aPh[2 * ss][1];
                const uint32_t ah2 = aPh[2 * ss + 1][0], ah3 = aPh[2 * ss + 1][1];
                const uint32_t al0 = aPl[2 * ss][0], al1 = aPl[2 * ss][1];
                const uint32_t al2 = aPl[2 * ss + 1][0], al3 = aPl[2 * ss + 1][1];
                int r = ss * 16 + (lane & 7) + ((lane >> 3) & 1) * 8;
#pragma unroll
                for (int dt = 0; dt < 8; dt++) {
                    int un = dt * 2 + ((lane >> 4) & 1);
                    uint32_t off = soff(r, un);
                    uint32_t vh4[4], vl4[4];
                    ldmx4t(vh4, kb + VO_H + off);
                    ldmx4t(vl4, kb + VO_L + off);
                    mma_bf16(o[2 * dt], ah0, ah1, ah2, ah3, vh4[0], vh4[1]);
                    mma_bf16(o[2 * dt], ah0, ah1, ah2, ah3, vl4[0], vl4[1]);
                    mma_bf16(o[2 * dt], al0, al1, al2, al3, vh4[0], vh4[1]);
                    mma_bf16(o[2 * dt + 1], ah0, ah1, ah2, ah3, vh4[2], vh4[3]);
                    mma_bf16(o[2 * dt + 1], ah0, ah1, ah2, ah3, vl4[2], vl4[3]);
                    mma_bf16(o[2 * dt + 1], al0, al1, al2, al3, vh4[2], vh4[3]);
                }
            }
        }
    }

    l0 += __shfl_xor_sync(0xffffffffu, l0, 1);
    l0 += __shfl_xor_sync(0xffffffffu, l0, 2);
    l1 += __shfl_xor_sync(0xffffffffu, l1, 1);
    l1 += __shfl_xor_sync(0xffffffffu, l1, 2);
    const float inv0 = 1.0f / l0, inv1 = 1.0f / l1;

    __nv_bfloat16* chiBase = g_chi + (size_t)h * HD;
    __nv_bfloat16* cloBase = g_clo + (size_t)h * HD;
    const size_t row0 = (size_t)(sg0 * BATCH + b) * HID;
    const size_t row1 = (size_t)(sg1 * BATCH + b) * HID;
#pragma unroll
    for (int jd = 0; jd < 16; jd++) {
        const int d = jd * 8 + 2 * lr;
        float v0 = o[jd][0] * inv0, v1 = o[jd][1] * inv0;
        float v2 = o[jd][2] * inv1, v3 = o[jd][3] * inv1;
        __nv_bfloat162 h01 = __floats2bfloat162_rn(v0, v1);
        __nv_bfloat162 l01 = __floats2bfloat162_rn(
            v0 - __bfloat162float(h01.x), v1 - __bfloat162float(h01.y));
        __nv_bfloat162 h23 = __floats2bfloat162_rn(v2, v3);
        __nv_bfloat162 l23 = __floats2bfloat162_rn(
            v2 - __bfloat162float(h23.x), v3 - __bfloat162float(h23.y));
        *(__nv_bfloat162*)(chiBase + row0 + d) = h01;
        *(__nv_bfloat162*)(cloBase + row0 + d) = l01;
        *(__nv_bfloat162*)(chiBase + row1 + d) = h23;
        *(__nv_bfloat162*)(cloBase + row1 + d) = l23;
    }
}

__global__ void copy_bias_kernel(const float* __restrict__ bias, float* __restrict__ dst)
{
    int i = blockIdx.x * blockDim.x + threadIdx.x;
    if (i < HID) dst[i] = bias[i];
}

// ---------------------------------------------------------------------------
extern "C" void kernel_launch(void* const* d_in, const int* in_sizes, int n_in,
                              void* d_out, int out_size)
{
    const float* hidden   = (const float*)d_in[0];
    const unsigned char* mask = (const unsigned char*)d_in[1];
    const float* qkv_w    = (const float*)d_in[2];
    const float* qkv_b    = (const float*)d_in[3];
    const float* proj_w   = (const float*)d_in[4];
    const float* proj_b   = (const float*)d_in[5];
    float* out = (float*)d_out;

    cudaFuncSetAttribute(attn_mma_kernel,
                         cudaFuncAttributeMaxDynamicSharedMemorySize, A2_SMEM);
    cudaFuncSetAttribute(gemm_hmma_kernel<N3H, 0>,
                         cudaFuncAttributeMaxDynamicSharedMemorySize, GEMM_DSMEM);
    cudaFuncSetAttribute(gemm_hmma_kernel<HID, 1>,
                         cudaFuncAttributeMaxDynamicSharedMemorySize, GEMM_DSMEM);

    // 1. prep splits
    split_hidden_kernel<<<M_ROWS * HID / 256, 256>>>(hidden);
    transpose_split_kernel<N3H, 0><<<dim3(N3H / 32, HID / 32), dim3(32, 8)>>>(qkv_w);
    transpose_split_kernel<HID, 1><<<dim3(HID / 32, HID / 32), dim3(32, 8)>>>(proj_w);

    // 2. QKV GEMM -> bf16 hi/lo q/k/v
    gemm_hmma_kernel<N3H, 0><<<dim3(N3H / 128, M_ROWS / 128), 256, GEMM_DSMEM>>>(qkv_b, nullptr);

    // 3. MMA flash attention v2 -> bf16 hi/lo ctx
    attn_mma_kernel<<<NBH * NQT2, 256, A2_SMEM>>>(mask);

    // 4. proj GEMM -> out
    gemm_hmma_kernel<HID, 1><<<dim3(HID / 128, M_ROWS / 128), 256, GEMM_DSMEM>>>(nullptr, out);

    if (out_size > M_ROWS * HID) {
        copy_bias_kernel<<<(HID + 255) / 256, 256>>>(proj_b, out + (size_t)M_ROWS * HID);
    }
}

// round 14
// speedup vs baseline: 5.0300x; 1.0512x over previous
#include <cuda_runtime.h>
#include <cuda_bf16.h>
#include <math.h>
#include <stdint.h>

#define S_LEN 2048
#define BATCH 2
#define HID   2048
#define NH    16
#define HD    128
#define M_ROWS (S_LEN * BATCH)   // 4096
#define N3H    (3 * HID)         // 6144
#define NBH    (BATCH * NH)      // 32

// ---------------------------------------------------------------------------
// Device-global scratch (allocation-free). All attention operands bf16 hi/lo.
// ---------------------------------------------------------------------------
__device__ __nv_bfloat16 g_qh[NBH * S_LEN * HD];
__device__ __nv_bfloat16 g_ql[NBH * S_LEN * HD];
__device__ __nv_bfloat16 g_kh[NBH * S_LEN * HD];
__device__ __nv_bfloat16 g_kl[NBH * S_LEN * HD];
__device__ __nv_bfloat16 g_vh[NBH * S_LEN * HD];
__device__ __nv_bfloat16 g_vl[NBH * S_LEN * HD];
__device__ __nv_bfloat16 g_chi[M_ROWS * HID];
__device__ __nv_bfloat16 g_clo[M_ROWS * HID];

__device__ __nv_bfloat16 g_ahi[M_ROWS * HID];       // hidden split
__device__ __nv_bfloat16 g_alo[M_ROWS * HID];
__device__ __nv_bfloat16 g_wqh[(size_t)N3H * HID];  // qkv_w^T split
__device__ __nv_bfloat16 g_wql[(size_t)N3H * HID];
__device__ __nv_bfloat16 g_wph[(size_t)HID * HID];  // proj_w^T split
__device__ __nv_bfloat16 g_wpl[(size_t)HID * HID];

// ---------------------------------------------------------------------------
// MMA / ldmatrix / cp.async helpers
// ---------------------------------------------------------------------------
__device__ __forceinline__ uint32_t smem_u32(const void* p) {
    uint32_t a;
    asm("{ .reg .u64 t; cvta.to.shared.u64 t, %1; cvt.u32.u64 %0, t; }"
        : "=r"(a) : "l"(p));
    return a;
}
__device__ __forceinline__ void ldmx4(uint32_t r[4], uint32_t addr) {
    asm volatile("ldmatrix.sync.aligned.m8n8.x4.shared.b16 {%0,%1,%2,%3}, [%4];"
                 : "=r"(r[0]), "=r"(r[1]), "=r"(r[2]), "=r"(r[3]) : "r"(addr));
}
__device__ __forceinline__ void ldmx4t(uint32_t r[4], uint32_t addr) {
    asm volatile("ldmatrix.sync.aligned.m8n8.x4.trans.shared.b16 {%0,%1,%2,%3}, [%4];"
                 : "=r"(r[0]), "=r"(r[1]), "=r"(r[2]), "=r"(r[3]) : "r"(addr));
}
__device__ __forceinline__ void mma_bf16(float c[4],
                                         uint32_t a0, uint32_t a1, uint32_t a2, uint32_t a3,
                                         uint32_t b0, uint32_t b1) {
    asm volatile(
        "mma.sync.aligned.m16n8k16.row.col.f32.bf16.bf16.f32 "
        "{%0,%1,%2,%3}, {%4,%5,%6,%7}, {%8,%9}, {%0,%1,%2,%3};"
        : "+f"(c[0]), "+f"(c[1]), "+f"(c[2]), "+f"(c[3])
        : "r"(a0), "r"(a1), "r"(a2), "r"(a3), "r"(b0), "r"(b1));
}
__device__ __forceinline__ void cp16(uint32_t saddr, const void* g) {
    asm volatile("cp.async.cg.shared.global [%0], [%1], 16;" :: "r"(saddr), "l"(g));
}
#define CP_COMMIT() asm volatile("cp.async.commit_group;" ::: "memory")
#define CP_WAIT(n)  asm volatile("cp.async.wait_group %0;" :: "n"(n) : "memory")

// ---------------------------------------------------------------------------
// Split prep kernels
// ---------------------------------------------------------------------------
__global__ void split_hidden_kernel(const float* __restrict__ in)
{
    int i = blockIdx.x * blockDim.x + threadIdx.x;
    float x = in[i];
    __nv_bfloat16 h = __float2bfloat16(x);
    g_ahi[i] = h;
    g_alo[i] = __float2bfloat16(x - __bfloat162float(h));
}

template<int NIN, int WSEL>
__global__ void transpose_split_kernel(const float* __restrict__ W)
{
    __shared__ float s[32][33];
    const int tx = threadIdx.x, ty = threadIdx.y;
    const int n0 = blockIdx.x * 32, k0 = blockIdx.y * 32;
    __nv_bfloat16* outHi = (WSEL == 0) ? g_wqh : g_wph;
    __nv_bfloat16* outLo = (WSEL == 0) ? g_wql : g_wpl;
#pragma unroll
    for (int i = 0; i < 4; i++) {
        int k = k0 + ty + i * 8;
        s[ty + i * 8][tx] = W[(size_t)k * NIN + n0 + tx];
    }
    __syncthreads();
#pragma unroll
    for (int i = 0; i < 4; i++) {
        int n = n0 + ty + i * 8;
        int k = k0 + tx;
        float x = s[tx][ty + i * 8];
        __nv_bfloat16 h = __float2bfloat16(x);
        outHi[(size_t)n * HID + k] = h;
        outLo[(size_t)n * HID + k] = __float2bfloat16(x - __bfloat162float(h));
    }
}

// ---------------------------------------------------------------------------
// bf16x3 HMMA GEMM with 3-stage cp.async pipeline (validated R11).
// ---------------------------------------------------------------------------
#define O_AH 0
#define O_AL 8192
#define O_BH 16384
#define O_BL 24576
#define STAGE_B 32768
#define NSTAGE 3
#define GEMM_DSMEM (NSTAGE * STAGE_B)   // 98304

__device__ __forceinline__ uint32_t swz_off(int row, int unit) {
    return (uint32_t)(row * 64 + ((unit ^ ((row >> 1) & 3)) << 4));
}

template<int NDIM, int SRC>
__global__ __launch_bounds__(256, 2) void gemm_hmma_kernel(
    const float* __restrict__ bias, float* __restrict__ out)
{
    extern __shared__ char smem[];
    const uint32_t sbase = smem_u32(smem);

    const int tid  = threadIdx.x;
    const int lane = tid & 31;
    const int wid  = tid >> 5;
    const int wRow = wid >> 2;
    const int wCol = wid & 3;
    const int rowBase = blockIdx.y * 128;
    const int colBase = blockIdx.x * 128;

    const __nv_bfloat16* Ahi = (SRC == 0) ? g_ahi : g_chi;
    const __nv_bfloat16* Alo = (SRC == 0) ? g_alo : g_clo;
    const __nv_bfloat16* Bhi = (SRC == 0) ? g_wqh : g_wph;
    const __nv_bfloat16* Blo = (SRC == 0) ? g_wql : g_wpl;

    float c[4][4][4];
#pragma unroll
    for (int i = 0; i < 4; i++)
#pragma unroll
        for (int j = 0; j < 4; j++)
#pragma unroll
            for (int e = 0; e < 4; e++) c[i][j][e] = 0.0f;

    int uRow[2], uUnit[2];
    uint32_t uSwz[2];
    size_t aOff0[2], bOff0[2];
#pragma unroll
    for (int i = 0; i < 2; i++) {
        int u = tid + i * 256;
        uRow[i]  = u >> 2;
        uUnit[i] = u & 3;
        uSwz[i]  = swz_off(uRow[i], uUnit[i]);
        aOff0[i] = (size_t)(rowBase + uRow[i]) * HID + uUnit[i] * 8;
        bOff0[i] = (size_t)(colBase + uRow[i]) * HID + uUnit[i] * 8;
    }

    const int aRowLane  = lane & 15;
    const int aUnitSel  = lane >> 4;
    const int bRowLane  = (lane & 7) + ((lane >> 4) & 1) * 8;
    const int bUnitSel  = (lane >> 3) & 1;

    uint32_t aAddrBase[4], bAddrBase[2];
    int aMask[4], bMask[2];
#pragma unroll
    for (int i = 0; i < 4; i++) {
        int r = wRow * 64 + i * 16 + aRowLane;
        aMask[i] = (r >> 1) & 3;
        aAddrBase[i] = (uint32_t)(r * 64);
    }
#pragma unroll
    for (int j2 = 0; j2 < 2; j2++) {
        int r = wCol * 32 + j2 * 16 + bRowLane;
        bMask[j2] = (r >> 1) & 3;
        bAddrBase[j2] = (uint32_t)(r * 64);
    }

    const int NIT = HID / 32;   // 64

#pragma unroll
    for (int s = 0; s < NSTAGE - 1; s++) {
        const int k0 = s * 32;
        const uint32_t sp = sbase + s * STAGE_B;
#pragma unroll
        for (int i = 0; i < 2; i++) {
            cp16(sp + O_AH + uSwz[i], Ahi + aOff0[i] + k0);
            cp16(sp + O_AL + uSwz[i], Alo + aOff0[i] + k0);
            cp16(sp + O_BH + uSwz[i], Bhi + bOff0[i] + k0);
            cp16(sp + O_BL + uSwz[i], Blo + bOff0[i] + k0);
        }
        CP_COMMIT();
    }

    int buf = 0;
    for (int it = 0; it < NIT; ++it) {
        CP_WAIT(NSTAGE - 2);
        __syncthreads();

        if (it + NSTAGE - 1 < NIT) {
            const int k0 = (it + NSTAGE - 1) * 32;
            const uint32_t sp = sbase + ((it + NSTAGE - 1) % NSTAGE) * STAGE_B;
#pragma unroll
            for (int i = 0; i < 2; i++) {
                cp16(sp + O_AH + uSwz[i], Ahi + aOff0[i] + k0);
                cp16(sp + O_AL + uSwz[i], Alo + aOff0[i] + k0);
                cp16(sp + O_BH + uSwz[i], Bhi + bOff0[i] + k0);
                cp16(sp + O_BL + uSwz[i], Blo + bOff0[i] + k0);
            }
        }
        CP_COMMIT();

        const uint32_t sp = sbase + buf * STAGE_B;
#pragma unroll
        for (int ks = 0; ks < 2; ks++) {
            uint32_t Ah[4][4], Al[4][4], Bh[2][4], Bl[2][4];
#pragma unroll
            for (int i = 0; i < 4; i++) {
                uint32_t off = aAddrBase[i] +
                    (uint32_t)(((ks * 2 + aUnitSel) ^ aMask[i]) << 4);
                ldmx4(Ah[i], sp + O_AH + off);
                ldmx4(Al[i], sp + O_AL + off);
            }
#pragma unroll
            for (int j2 = 0; j2 < 2; j2++) {
                uint32_t off = bAddrBase[j2] +
                    (uint32_t)(((ks * 2 + bUnitSel) ^ bMask[j2]) << 4);
                ldmx4(Bh[j2], sp + O_BH + off);
                ldmx4(Bl[j2], sp + O_BL + off);
            }
#pragma unroll
            for (int i = 0; i < 4; i++)
#pragma unroll
                for (int j = 0; j < 4; j++) {
                    const int g = j >> 1, p = (j & 1) * 2;
                    mma_bf16(c[i][j], Ah[i][0], Ah[i][1], Ah[i][2], Ah[i][3],
                             Bh[g][p], Bh[g][p + 1]);
                    mma_bf16(c[i][j], Ah[i][0], Ah[i][1], Ah[i][2], Ah[i][3],
                             Bl[g][p], Bl[g][p + 1]);
                    mma_bf16(c[i][j], Al[i][0], Al[i][1], Al[i][2], Al[i][3],
                             Bh[g][p], Bh[g][p + 1]);
                }
        }
        buf = (buf + 1 == NSTAGE) ? 0 : buf + 1;
    }

    const int lq = lane >> 2;
    const int lr = lane & 3;
#pragma unroll
    for (int i = 0; i < 4; i++) {
        const int r0 = rowBase + wRow * 64 + i * 16 + lq;
#pragma unroll
        for (int j = 0; j < 4; j++) {
            const int cc = colBase + wCol * 32 + j * 8 + 2 * lr;
            if (SRC == 0) {
#pragma unroll
                for (int e = 0; e < 4; e++) {
                    const int r = r0 + (e >> 1) * 8;
                    const int col = cc + (e & 1);
                    const float v = c[i][j][e] + bias[col];
                    const int s = r >> 1;       // BATCH == 2
                    const int b = r & 1;
                    const int h = col / 384;
                    const int jj = col - h * 384;
                    const int which = jj >> 7;  // 0=q, 1=k, 2=v
                    const int dd = jj & 127;
                    __nv_bfloat16* ph = (which == 0) ? g_qh : (which == 1 ? g_kh : g_vh);
                    __nv_bfloat16* pl = (which == 0) ? g_ql : (which == 1 ? g_kl : g_vl);
                    const size_t idx = (size_t)(((b * NH + h) * S_LEN) + s) * HD + dd;
                    __nv_bfloat16 hh = __float2bfloat16(v);
                    ph[idx] = hh;
                    pl[idx] = __float2bfloat16(v - __bfloat162float(hh));
                }
            } else {
                float2 v0 = make_float2(c[i][j][0], c[i][j][1]);
                float2 v1 = make_float2(c[i][j][2], c[i][j][3]);
                *(float2*)(out + (size_t)r0 * NDIM + cc) = v0;
                *(float2*)(out + (size_t)(r0 + 8) * NDIM + cc) = v1;
            }
        }
    }
}

// ---------------------------------------------------------------------------
// MMA flash attention v2 + LPT ordering: 128-row Q tile, 256 threads
// (8 warps x 16 rows), double-buffered cp.async K/V, warp-uniform causal
// skip. Grid ordered qt-major DESCENDING (heaviest blocks launch first,
// lightest last) so the scheduling tail is one light block, not a 32-tile
// straggler.
// ---------------------------------------------------------------------------
#define ATQ2 128
#define NQT2 (S_LEN / ATQ2)       // 16
#define SQ2_H 0
#define SQ2_L 32768
#define SKV0  65536               // stage base; stage stride 65536
#define KO_H  0
#define KO_L  16384
#define VO_H  32768
#define VO_L  49152
#define A2_SMEM (65536 + 2 * 65536)   // 196608

__device__ __forceinline__ uint32_t soff(int row, int unit) {
    return (uint32_t)(row * 256 + ((unit ^ (row & 7)) << 4));
}

__global__ __launch_bounds__(256, 1) void attn_mma_kernel(
    const unsigned char* __restrict__ mask)
{
    extern __shared__ char sm8[];
    const uint32_t sb = smem_u32(sm8);

    const int bid = blockIdx.x;
    // LPT: qt-major descending, bh-minor. bids 0..31 -> qt=15 (heaviest),
    // bids 480..511 -> qt=0 (lightest).
    const int qt = NQT2 - 1 - (bid >> 5);
    const int bh = bid & 31;
    const int b = bh / NH;
    const int h = bh % NH;
    const int q0 = qt * ATQ2;
    const int NKT = 2 * qt + 2;               // 64-key tiles covering [0, q0+128)

    const int tid = threadIdx.x;
    const int lane = tid & 31;
    const int w = tid >> 5;                   // warp 0..7 -> rows w*16..w*16+15
    const int lq = lane >> 2;
    const int lr = lane & 3;
    const float inv_norm = 0.08838834764831845f;

    const __nv_bfloat16* KhB = g_kh + (size_t)bh * S_LEN * HD;
    const __nv_bfloat16* KlB = g_kl + (size_t)bh * S_LEN * HD;
    const __nv_bfloat16* VhB = g_vh + (size_t)bh * S_LEN * HD;
    const __nv_bfloat16* VlB = g_vl + (size_t)bh * S_LEN * HD;

    // per-thread cp.async geometry for one 64x128 bf16 tile (16KB)
    int cRow[4], cUn[4];
    uint32_t cSwz[4];
#pragma unroll
    for (int i = 0; i < 4; i++) {
        int u = tid + i * 256;
        cRow[i] = u >> 4;
        cUn[i]  = u & 15;
        cSwz[i] = soff(cRow[i], cUn[i]);
    }

    // issue stage 0 (kt = 0)
    {
        const uint32_t sp = sb + SKV0;
#pragma unroll
        for (int i = 0; i < 4; i++) {
            const size_t g = (size_t)cRow[i] * HD + cUn[i] * 8;
            cp16(sp + KO_H + cSwz[i], KhB + g);
            cp16(sp + KO_L + cSwz[i], KlB + g);
            cp16(sp + VO_H + cSwz[i], VhB + g);
            cp16(sp + VO_L + cSwz[i], VlB + g);
        }
        CP_COMMIT();
    }

    // load Q tile (plain loads; overlaps with stage-0 cp.async)
    {
        const __nv_bfloat16* Qh = g_qh + ((size_t)bh * S_LEN + q0) * HD;
        const __nv_bfloat16* Ql = g_ql + ((size_t)bh * S_LEN + q0) * HD;
#pragma unroll
        for (int i = 0; i < 8; i++) {
            int u = tid + i * 256;
            int row = u >> 4, un = u & 15;
            uint32_t off = soff(row, un);
            *(uint4*)(sm8 + SQ2_H + off) = ((const uint4*)(Qh + row * HD))[un];
            *(uint4*)(sm8 + SQ2_L + off) = ((const uint4*)(Ql + row * HD))[un];
        }
    }

    const int sg0 = q0 + w * 16 + lq;
    const int sg1 = sg0 + 8;
    const int wRowMax = q0 + w * 16 + 15;
    const unsigned char* mrow0 = mask + ((size_t)b * S_LEN + sg0) * S_LEN;
    const unsigned char* mrow1 = mask + ((size_t)b * S_LEN + sg1) * S_LEN;

    float m0 = -1e30f, m1 = -1e30f, l0 = 0.0f, l1 = 0.0f;
    float o[16][4];
#pragma unroll
    for (int jd = 0; jd < 16; jd++)
#pragma unroll
        for (int e = 0; e < 4; e++) o[jd][e] = 0.0f;

    for (int kt = 0; kt < NKT; ++kt) {
        __syncthreads();   // all warps done reading buffer (kt-1)&1 before refill

        if (kt + 1 < NKT) {
            const uint32_t sp = sb + SKV0 + ((kt + 1) & 1) * 65536;
            const size_t kbase = (size_t)(kt + 1) * 64 * HD;
#pragma unroll
            for (int i = 0; i < 4; i++) {
                const size_t g = kbase + (size_t)cRow[i] * HD + cUn[i] * 8;
                cp16(sp + KO_H + cSwz[i], KhB + g);
                cp16(sp + KO_L + cSwz[i], KlB + g);
                cp16(sp + VO_H + cSwz[i], VhB + g);
                cp16(sp + VO_L + cSwz[i], VlB + g);
            }
            CP_COMMIT();
            CP_WAIT(1);
        } else {
            CP_WAIT(0);
        }
        __syncthreads();   // kt's data visible to all warps

        const int k0 = kt * 64;
        if (k0 <= wRowMax) {   // warp-uniform causal skip
            const uint32_t kb = sb + SKV0 + (kt & 1) * 65536;

            float c[8][4];
#pragma unroll
            for (int j = 0; j < 8; j++)
#pragma unroll
                for (int e = 0; e < 4; e++) c[j][e] = 0.0f;

#pragma unroll
            for (int ks = 0; ks < 8; ks++) {
                uint32_t qh4[4], ql4[4];
                {
                    int r = w * 16 + (lane & 15);
                    int un = ks * 2 + (lane >> 4);
                    uint32_t off = soff(r, un);
                    ldmx4(qh4, sb + SQ2_H + off);
                    ldmx4(ql4, sb + SQ2_L + off);
                }
#pragma unroll
                for (int nt = 0; nt < 4; nt++) {
                    int r = nt * 16 + (lane & 7) + ((lane >> 4) & 1) * 8;
                    int un = ks * 2 + ((lane >> 3) & 1);
                    uint32_t off = soff(r, un);
                    uint32_t kh4[4], kl4[4];
                    ldmx4(kh4, kb + KO_H + off);
                    ldmx4(kl4, kb + KO_L + off);
                    mma_bf16(c[2 * nt], qh4[0], qh4[1], qh4[2], qh4[3], kh4[0], kh4[1]);
                    mma_bf16(c[2 * nt], qh4[0], qh4[1], qh4[2], qh4[3], kl4[0], kl4[1]);
                    mma_bf16(c[2 * nt], ql4[0], ql4[1], ql4[2], ql4[3], kh4[0], kh4[1]);
                    mma_bf16(c[2 * nt + 1], qh4[0], qh4[1], qh4[2], qh4[3], kh4[2], kh4[3]);
                    mma_bf16(c[2 * nt + 1], qh4[0], qh4[1], qh4[2], qh4[3], kl4[2], kl4[3]);
                    mma_bf16(c[2 * nt + 1], ql4[0], ql4[1], ql4[2], ql4[3], kh4[2], kh4[3]);
                }
            }

#pragma unroll
            for (int j = 0; j < 8; j++) {
                const int t0 = k0 + j * 8 + 2 * lr;
                uchar2 mb0 = *(const uchar2*)(mrow0 + t0);
                uchar2 mb1 = *(const uchar2*)(mrow1 + t0);
                c[j][0] = (t0 > sg0     || mb0.x) ? -10000.0f : c[j][0] * inv_norm;
                c[j][1] = (t0 + 1 > sg0 || mb0.y) ? -10000.0f : c[j][1] * inv_norm;
                c[j][2] = (t0 > sg1     || mb1.x) ? -10000.0f : c[j][2] * inv_norm;
                c[j][3] = (t0 + 1 > sg1 || mb1.y) ? -10000.0f : c[j][3] * inv_norm;
            }

            float vm0 = -1e30f, vm1 = -1e30f;
#pragma unroll
            for (int j = 0; j < 8; j++) {
                vm0 = fmaxf(vm0, fmaxf(c[j][0], c[j][1]));
                vm1 = fmaxf(vm1, fmaxf(c[j][2], c[j][3]));
            }
            vm0 = fmaxf(vm0, __shfl_xor_sync(0xffffffffu, vm0, 1));
            vm0 = fmaxf(vm0, __shfl_xor_sync(0xffffffffu, vm0, 2));
            vm1 = fmaxf(vm1, __shfl_xor_sync(0xffffffffu, vm1, 1));
            vm1 = fmaxf(vm1, __shfl_xor_sync(0xffffffffu, vm1, 2));
            const float mn0 = fmaxf(m0, vm0), mn1 = fmaxf(m1, vm1);
            const float cor0 = __expf(m0 - mn0), cor1 = __expf(m1 - mn1);
            m0 = mn0; m1 = mn1;

            uint32_t aPh[8][2], aPl[8][2];
            float ls0 = 0.0f, ls1 = 0.0f;
#pragma unroll
            for (int j = 0; j < 8; j++) {
                float p0 = __expf(c[j][0] - mn0);
                float p1 = __expf(c[j][1] - mn0);
                float p2 = __expf(c[j][2] - mn1);
                float p3 = __expf(c[j][3] - mn1);
                ls0 += p0 + p1; ls1 += p2 + p3;
                __nv_bfloat162 h01 = __floats2bfloat162_rn(p0, p1);
                __nv_bfloat162 h23 = __floats2bfloat162_rn(p2, p3);
                __nv_bfloat162 l01 = __floats2bfloat162_rn(
                    p0 - __bfloat162float(h01.x), p1 - __bfloat162float(h01.y));
                __nv_bfloat162 l23 = __floats2bfloat162_rn(
                    p2 - __bfloat162float(h23.x), p3 - __bfloat162float(h23.y));
                aPh[j][0] = *(uint32_t*)&h01;
                aPh[j][1] = *(uint32_t*)&h23;
                aPl[j][0] = *(uint32_t*)&l01;
                aPl[j][1] = *(uint32_t*)&l23;
            }
            l0 = l0 * cor0 + ls0;
            l1 = l1 * cor1 + ls1;
#pragma unroll
            for (int jd = 0; jd < 16; jd++) {
                o[jd][0] *= cor0; o[jd][1] *= cor0;
                o[jd][2] *= cor1; o[jd][3] *= cor1;
            }

#pragma unroll
            for (int ss = 0; ss < 4; ss++) {
                const uint32_t ah0 = aPh[2 * ss][0], ah1 = aPh[2 * ss][1];
                const uint32_t ah2 = aPh[2 * ss + 1][0], ah3 = aPh[2 * ss + 1][1];
                const uint32_t al0 = aPl[2 * ss][0], al1 = aPl[2 * ss][1];
                const uint32_t al2 = aPl[2 * ss + 1][0], al3 = aPl[2 * ss + 1][1];
                int r = ss * 16 + (lane & 7) + ((lane >> 3) & 1) * 8;
#pragma unroll
                for (int dt = 0; dt < 8; dt++) {
                    int un = dt * 2 + ((lane >> 4) & 1);
                    uint32_t off = soff(r, un);
                    uint32_t vh4[4], vl4[4];
                    ldmx4t(vh4, kb + VO_H + off);
                    ldmx4t(vl4, kb + VO_L + off);
                    mma_bf16(o[2 * dt], ah0, ah1, ah2, ah3, vh4[0], vh4[1]);
                    mma_bf16(o[2 * dt], ah0, ah1, ah2, ah3, vl4[0], vl4[1]);
                    mma_bf16(o[2 * dt], al0, al1, al2, al3, vh4[0], vh4[1]);
                    mma_bf16(o[2 * dt + 1], ah0, ah1, ah2, ah3, vh4[2], vh4[3]);
                    mma_bf16(o[2 * dt + 1], ah0, ah1, ah2, ah3, vl4[2], vl4[3]);
                    mma_bf16(o[2 * dt + 1], al0, al1, al2, al3, vh4[2], vh4[3]);
                }
            }
        }
    }

    l0 += __shfl_xor_sync(0xffffffffu, l0, 1);
    l0 += __shfl_xor_sync(0xffffffffu, l0, 2);
    l1 += __shfl_xor_sync(0xffffffffu, l1, 1);
    l1 += __shfl_xor_sync(0xffffffffu, l1, 2);
    const float inv0 = 1.0f / l0, inv1 = 1.0f / l1;

    __nv_bfloat16* chiBase = g_chi + (size_t)h * HD;
    __nv_bfloat16* cloBase = g_clo + (size_t)h * HD;
    const size_t row0 = (size_t)(sg0 * BATCH + b) * HID;
    const size_t row1 = (size_t)(sg1 * BATCH + b) * HID;
#pragma unroll
    for (int jd = 0; jd < 16; jd++) {
        const int d = jd * 8 + 2 * lr;
        float v0 = o[jd][0] * inv0, v1 = o[jd][1] * inv0;
        float v2 = o[jd][2] * inv1, v3 = o[jd][3] * inv1;
        __nv_bfloat162 h01 = __floats2bfloat162_rn(v0, v1);
        __nv_bfloat162 l01 = __floats2bfloat162_rn(
            v0 - __bfloat162float(h01.x), v1 - __bfloat162float(h01.y));
        __nv_bfloat162 h23 = __floats2bfloat162_rn(v2, v3);
        __nv_bfloat162 l23 = __floats2bfloat162_rn(
            v2 - __bfloat162float(h23.x), v3 - __bfloat162float(h23.y));
        *(__nv_bfloat162*)(chiBase + row0 + d) = h01;
        *(__nv_bfloat162*)(cloBase + row0 + d) = l01;
        *(__nv_bfloat162*)(chiBase + row1 + d) = h23;
        *(__nv_bfloat162*)(cloBase + row1 + d) = l23;
    }
}

__global__ void copy_bias_kernel(const float* __restrict__ bias, float* __restrict__ dst)
{
    int i = blockIdx.x * blockDim.x + threadIdx.x;
    if (i < HID) dst[i] = bias[i];
}

// ---------------------------------------------------------------------------
extern "C" void kernel_launch(void* const* d_in, const int* in_sizes, int n_in,
                              void* d_out, int out_size)
{
    const float* hidden   = (const float*)d_in[0];
    const unsigned char* mask = (const unsigned char*)d_in[1];
    const float* qkv_w    = (const float*)d_in[2];
    const float* qkv_b    = (const float*)d_in[3];
    const float* proj_w   = (const float*)d_in[4];
    const float* proj_b   = (const float*)d_in[5];
    float* out = (float*)d_out;

    cudaFuncSetAttribute(attn_mma_kernel,
                         cudaFuncAttributeMaxDynamicSharedMemorySize, A2_SMEM);
    cudaFuncSetAttribute(gemm_hmma_kernel<N3H, 0>,
                         cudaFuncAttributeMaxDynamicSharedMemorySize, GEMM_DSMEM);
    cudaFuncSetAttribute(gemm_hmma_kernel<HID, 1>,
                         cudaFuncAttributeMaxDynamicSharedMemorySize, GEMM_DSMEM);

    // 1. prep splits
    split_hidden_kernel<<<M_ROWS * HID / 256, 256>>>(hidden);
    transpose_split_kernel<N3H, 0><<<dim3(N3H / 32, HID / 32), dim3(32, 8)>>>(qkv_w);
    transpose_split_kernel<HID, 1><<<dim3(HID / 32, HID / 32), dim3(32, 8)>>>(proj_w);

    // 2. QKV GEMM -> bf16 hi/lo q/k/v
    gemm_hmma_kernel<N3H, 0><<<dim3(N3H / 128, M_ROWS / 128), 256, GEMM_DSMEM>>>(qkv_b, nullptr);

    // 3. MMA flash attention (LPT-ordered) -> bf16 hi/lo ctx
    attn_mma_kernel<<<NBH * NQT2, 256, A2_SMEM>>>(mask);

    // 4. proj GEMM -> out
    gemm_hmma_kernel<HID, 1><<<dim3(HID / 128, M_ROWS / 128), 256, GEMM_DSMEM>>>(nullptr, out);

    if (out_size > M_ROWS * HID) {
        copy_bias_kernel<<<(HID + 255) / 256, 256>>>(proj_b, out + (size_t)M_ROWS * HID);
    }
}

// round 15
// speedup vs baseline: 5.2952x; 1.0527x over previous
#include <cuda_runtime.h>
#include <cuda_bf16.h>
#include <math.h>
#include <stdint.h>

#define S_LEN 2048
#define BATCH 2
#define HID   2048
#define NH    16
#define HD    128
#define M_ROWS (S_LEN * BATCH)   // 4096
#define N3H    (3 * HID)         // 6144
#define NBH    (BATCH * NH)      // 32

// ---------------------------------------------------------------------------
// Device-global scratch (allocation-free). All attention operands bf16 hi/lo.
// ---------------------------------------------------------------------------
__device__ __nv_bfloat16 g_qh[NBH * S_LEN * HD];
__device__ __nv_bfloat16 g_ql[NBH * S_LEN * HD];
__device__ __nv_bfloat16 g_kh[NBH * S_LEN * HD];
__device__ __nv_bfloat16 g_kl[NBH * S_LEN * HD];
__device__ __nv_bfloat16 g_vh[NBH * S_LEN * HD];
__device__ __nv_bfloat16 g_vl[NBH * S_LEN * HD];
__device__ __nv_bfloat16 g_chi[M_ROWS * HID];
__device__ __nv_bfloat16 g_clo[M_ROWS * HID];

__device__ __nv_bfloat16 g_ahi[M_ROWS * HID];       // hidden split
__device__ __nv_bfloat16 g_alo[M_ROWS * HID];
__device__ __nv_bfloat16 g_wqh[(size_t)N3H * HID];  // qkv_w^T split
__device__ __nv_bfloat16 g_wql[(size_t)N3H * HID];
__device__ __nv_bfloat16 g_wph[(size_t)HID * HID];  // proj_w^T split
__device__ __nv_bfloat16 g_wpl[(size_t)HID * HID];

// ---------------------------------------------------------------------------
// MMA / ldmatrix / cp.async helpers
// ---------------------------------------------------------------------------
__device__ __forceinline__ uint32_t smem_u32(const void* p) {
    uint32_t a;
    asm("{ .reg .u64 t; cvta.to.shared.u64 t, %1; cvt.u32.u64 %0, t; }"
        : "=r"(a) : "l"(p));
    return a;
}
__device__ __forceinline__ void ldmx4(uint32_t r[4], uint32_t addr) {
    asm volatile("ldmatrix.sync.aligned.m8n8.x4.shared.b16 {%0,%1,%2,%3}, [%4];"
                 : "=r"(r[0]), "=r"(r[1]), "=r"(r[2]), "=r"(r[3]) : "r"(addr));
}
__device__ __forceinline__ void ldmx4t(uint32_t r[4], uint32_t addr) {
    asm volatile("ldmatrix.sync.aligned.m8n8.x4.trans.shared.b16 {%0,%1,%2,%3}, [%4];"
                 : "=r"(r[0]), "=r"(r[1]), "=r"(r[2]), "=r"(r[3]) : "r"(addr));
}
__device__ __forceinline__ void mma_bf16(float c[4],
                                         uint32_t a0, uint32_t a1, uint32_t a2, uint32_t a3,
                                         uint32_t b0, uint32_t b1) {
    asm volatile(
        "mma.sync.aligned.m16n8k16.row.col.f32.bf16.bf16.f32 "
        "{%0,%1,%2,%3}, {%4,%5,%6,%7}, {%8,%9}, {%0,%1,%2,%3};"
        : "+f"(c[0]), "+f"(c[1]), "+f"(c[2]), "+f"(c[3])
        : "r"(a0), "r"(a1), "r"(a2), "r"(a3), "r"(b0), "r"(b1));
}
__device__ __forceinline__ void cp16(uint32_t saddr, const void* g) {
    asm volatile("cp.async.cg.shared.global [%0], [%1], 16;" :: "r"(saddr), "l"(g));
}
#define CP_COMMIT() asm volatile("cp.async.commit_group;" ::: "memory")
#define CP_WAIT(n)  asm volatile("cp.async.wait_group %0;" :: "n"(n) : "memory")

// ---------------------------------------------------------------------------
// Split prep kernels
// ---------------------------------------------------------------------------
__global__ void split_hidden_kernel(const float* __restrict__ in)
{
    int i = blockIdx.x * blockDim.x + threadIdx.x;
    float x = in[i];
    __nv_bfloat16 h = __float2bfloat16(x);
    g_ahi[i] = h;
    g_alo[i] = __float2bfloat16(x - __bfloat162float(h));
}

template<int NIN, int WSEL>
__global__ void transpose_split_kernel(const float* __restrict__ W)
{
    __shared__ float s[32][33];
    const int tx = threadIdx.x, ty = threadIdx.y;
    const int n0 = blockIdx.x * 32, k0 = blockIdx.y * 32;
    __nv_bfloat16* outHi = (WSEL == 0) ? g_wqh : g_wph;
    __nv_bfloat16* outLo = (WSEL == 0) ? g_wql : g_wpl;
#pragma unroll
    for (int i = 0; i < 4; i++) {
        int k = k0 + ty + i * 8;
        s[ty + i * 8][tx] = W[(size_t)k * NIN + n0 + tx];
    }
    __syncthreads();
#pragma unroll
    for (int i = 0; i < 4; i++) {
        int n = n0 + ty + i * 8;
        int k = k0 + tx;
        float x = s[tx][ty + i * 8];
        __nv_bfloat16 h = __float2bfloat16(x);
        outHi[(size_t)n * HID + k] = h;
        outLo[(size_t)n * HID + k] = __float2bfloat16(x - __bfloat162float(h));
    }
}

// ---------------------------------------------------------------------------
// bf16x3 HMMA GEMM with 3-stage cp.async pipeline (validated R11) +
// smem-staged coalesced epilogue for the QKV scatter (R15).
// ---------------------------------------------------------------------------
#define O_AH 0
#define O_AL 8192
#define O_BH 16384
#define O_BL 24576
#define STAGE_B 32768
#define NSTAGE 3
#define GEMM_DSMEM (NSTAGE * STAGE_B)   // 98304
#define EP_STR 136                       // bf16 stride for epilogue staging

__device__ __forceinline__ uint32_t swz_off(int row, int unit) {
    return (uint32_t)(row * 64 + ((unit ^ ((row >> 1) & 3)) << 4));
}

template<int NDIM, int SRC>
__global__ __launch_bounds__(256, 2) void gemm_hmma_kernel(
    const float* __restrict__ bias, float* __restrict__ out)
{
    extern __shared__ char smem[];
    const uint32_t sbase = smem_u32(smem);

    const int tid  = threadIdx.x;
    const int lane = tid & 31;
    const int wid  = tid >> 5;
    const int wRow = wid >> 2;
    const int wCol = wid & 3;
    const int rowBase = blockIdx.y * 128;
    const int colBase = blockIdx.x * 128;

    const __nv_bfloat16* Ahi = (SRC == 0) ? g_ahi : g_chi;
    const __nv_bfloat16* Alo = (SRC == 0) ? g_alo : g_clo;
    const __nv_bfloat16* Bhi = (SRC == 0) ? g_wqh : g_wph;
    const __nv_bfloat16* Blo = (SRC == 0) ? g_wql : g_wpl;

    float c[4][4][4];
#pragma unroll
    for (int i = 0; i < 4; i++)
#pragma unroll
        for (int j = 0; j < 4; j++)
#pragma unroll
            for (int e = 0; e < 4; e++) c[i][j][e] = 0.0f;

    int uRow[2], uUnit[2];
    uint32_t uSwz[2];
    size_t aOff0[2], bOff0[2];
#pragma unroll
    for (int i = 0; i < 2; i++) {
        int u = tid + i * 256;
        uRow[i]  = u >> 2;
        uUnit[i] = u & 3;
        uSwz[i]  = swz_off(uRow[i], uUnit[i]);
        aOff0[i] = (size_t)(rowBase + uRow[i]) * HID + uUnit[i] * 8;
        bOff0[i] = (size_t)(colBase + uRow[i]) * HID + uUnit[i] * 8;
    }

    const int aRowLane  = lane & 15;
    const int aUnitSel  = lane >> 4;
    const int bRowLane  = (lane & 7) + ((lane >> 4) & 1) * 8;
    const int bUnitSel  = (lane >> 3) & 1;

    uint32_t aAddrBase[4], bAddrBase[2];
    int aMask[4], bMask[2];
#pragma unroll
    for (int i = 0; i < 4; i++) {
        int r = wRow * 64 + i * 16 + aRowLane;
        aMask[i] = (r >> 1) & 3;
        aAddrBase[i] = (uint32_t)(r * 64);
    }
#pragma unroll
    for (int j2 = 0; j2 < 2; j2++) {
        int r = wCol * 32 + j2 * 16 + bRowLane;
        bMask[j2] = (r >> 1) & 3;
        bAddrBase[j2] = (uint32_t)(r * 64);
    }

    const int NIT = HID / 32;   // 64

#pragma unroll
    for (int s = 0; s < NSTAGE - 1; s++) {
        const int k0 = s * 32;
        const uint32_t sp = sbase + s * STAGE_B;
#pragma unroll
        for (int i = 0; i < 2; i++) {
            cp16(sp + O_AH + uSwz[i], Ahi + aOff0[i] + k0);
            cp16(sp + O_AL + uSwz[i], Alo + aOff0[i] + k0);
            cp16(sp + O_BH + uSwz[i], Bhi + bOff0[i] + k0);
            cp16(sp + O_BL + uSwz[i], Blo + bOff0[i] + k0);
        }
        CP_COMMIT();
    }

    int buf = 0;
    for (int it = 0; it < NIT; ++it) {
        CP_WAIT(NSTAGE - 2);
        __syncthreads();

        if (it + NSTAGE - 1 < NIT) {
            const int k0 = (it + NSTAGE - 1) * 32;
            const uint32_t sp = sbase + ((it + NSTAGE - 1) % NSTAGE) * STAGE_B;
#pragma unroll
            for (int i = 0; i < 2; i++) {
                cp16(sp + O_AH + uSwz[i], Ahi + aOff0[i] + k0);
                cp16(sp + O_AL + uSwz[i], Alo + aOff0[i] + k0);
                cp16(sp + O_BH + uSwz[i], Bhi + bOff0[i] + k0);
                cp16(sp + O_BL + uSwz[i], Blo + bOff0[i] + k0);
            }
        }
        CP_COMMIT();

        const uint32_t sp = sbase + buf * STAGE_B;
#pragma unroll
        for (int ks = 0; ks < 2; ks++) {
            uint32_t Ah[4][4], Al[4][4], Bh[2][4], Bl[2][4];
#pragma unroll
            for (int i = 0; i < 4; i++) {
                uint32_t off = aAddrBase[i] +
                    (uint32_t)(((ks * 2 + aUnitSel) ^ aMask[i]) << 4);
                ldmx4(Ah[i], sp + O_AH + off);
                ldmx4(Al[i], sp + O_AL + off);
            }
#pragma unroll
            for (int j2 = 0; j2 < 2; j2++) {
                uint32_t off = bAddrBase[j2] +
                    (uint32_t)(((ks * 2 + bUnitSel) ^ bMask[j2]) << 4);
                ldmx4(Bh[j2], sp + O_BH + off);
                ldmx4(Bl[j2], sp + O_BL + off);
            }
#pragma unroll
            for (int i = 0; i < 4; i++)
#pragma unroll
                for (int j = 0; j < 4; j++) {
                    const int g = j >> 1, p = (j & 1) * 2;
                    mma_bf16(c[i][j], Ah[i][0], Ah[i][1], Ah[i][2], Ah[i][3],
                             Bh[g][p], Bh[g][p + 1]);
                    mma_bf16(c[i][j], Ah[i][0], Ah[i][1], Ah[i][2], Ah[i][3],
                             Bl[g][p], Bl[g][p + 1]);
                    mma_bf16(c[i][j], Al[i][0], Al[i][1], Al[i][2], Al[i][3],
                             Bh[g][p], Bh[g][p + 1]);
                }
        }
        buf = (buf + 1 == NSTAGE) ? 0 : buf + 1;
    }

    const int lq = lane >> 2;
    const int lr = lane & 3;

    if (SRC == 0) {
        // ---- staged epilogue: c -> smem [128][EP_STR] hi/lo -> coalesced gmem
        __syncthreads();   // stage buffers now reusable
        __nv_bfloat16* sH = (__nv_bfloat16*)smem;
        __nv_bfloat16* sL = (__nv_bfloat16*)(smem + 128 * EP_STR * 2);
#pragma unroll
        for (int i = 0; i < 4; i++) {
            const int rl = wRow * 64 + i * 16 + lq;
#pragma unroll
            for (int j = 0; j < 4; j++) {
                const int cl = wCol * 32 + j * 8 + 2 * lr;
                const float b0 = bias[colBase + cl];
                const float b1 = bias[colBase + cl + 1];
                const float v0 = c[i][j][0] + b0;
                const float v1 = c[i][j][1] + b1;
                const float v2 = c[i][j][2] + b0;
                const float v3 = c[i][j][3] + b1;
                __nv_bfloat162 h01 = __floats2bfloat162_rn(v0, v1);
                __nv_bfloat162 l01 = __floats2bfloat162_rn(
                    v0 - __bfloat162float(h01.x), v1 - __bfloat162float(h01.y));
                __nv_bfloat162 h23 = __floats2bfloat162_rn(v2, v3);
                __nv_bfloat162 l23 = __floats2bfloat162_rn(
                    v2 - __bfloat162float(h23.x), v3 - __bfloat162float(h23.y));
                *(__nv_bfloat162*)&sH[rl * EP_STR + cl] = h01;
                *(__nv_bfloat162*)&sL[rl * EP_STR + cl] = l01;
                *(__nv_bfloat162*)&sH[(rl + 8) * EP_STR + cl] = h23;
                *(__nv_bfloat162*)&sL[(rl + 8) * EP_STR + cl] = l23;
            }
        }
        __syncthreads();

        const int hBlk = colBase / 384;
        const int whichBlk = (colBase % 384) >> 7;   // 0=q, 1=k, 2=v
        __nv_bfloat16* dstH = (whichBlk == 0) ? g_qh : (whichBlk == 1 ? g_kh : g_vh);
        __nv_bfloat16* dstL = (whichBlk == 0) ? g_ql : (whichBlk == 1 ? g_kl : g_vl);
#pragma unroll
        for (int k = 0; k < 16; k++) {
            const int g = tid + k * 256;     // 0..4095
            const int arr = g >> 11;         // 0=hi 1=lo
            const int row = (g >> 4) & 127;
            const int u = g & 15;
            const int grow = rowBase + row;
            const int s = grow >> 1;         // BATCH == 2
            const int b = grow & 1;
            const __nv_bfloat16* src = (arr ? sL : sH) + row * EP_STR + u * 8;
            __nv_bfloat16* dst = (arr ? dstL : dstH) +
                ((size_t)(b * NH + hBlk) * S_LEN + s) * HD + u * 8;
            *(uint4*)dst = *(const uint4*)src;
        }
    } else {
#pragma unroll
        for (int i = 0; i < 4; i++) {
            const int r0 = rowBase + wRow * 64 + i * 16 + lq;
#pragma unroll
            for (int j = 0; j < 4; j++) {
                const int cc = colBase + wCol * 32 + j * 8 + 2 * lr;
                float2 v0 = make_float2(c[i][j][0], c[i][j][1]);
                float2 v1 = make_float2(c[i][j][2], c[i][j][3]);
                *(float2*)(out + (size_t)r0 * NDIM + cc) = v0;
                *(float2*)(out + (size_t)(r0 + 8) * NDIM + cc) = v1;
            }
        }
    }
}

// ---------------------------------------------------------------------------
// MMA flash attention v3: 128-row Q tile, 256 threads (8 warps x 16 rows),
// Q fragments in registers, 3-stage cp.async K/V pipeline (single barrier
// per tile), warp-uniform causal skip, LPT block ordering.
// ---------------------------------------------------------------------------
#define ATQ2 128
#define NQT2 (S_LEN / ATQ2)       // 16
#define AT_STAGE 65536            // one K/V stage: Kh,Kl,Vh,Vl 16KB each
#define KO_H  0
#define KO_L  16384
#define VO_H  32768
#define VO_L  49152
#define A3_SMEM (3 * AT_STAGE)    // 196608

__device__ __forceinline__ uint32_t soff(int row, int unit) {
    return (uint32_t)(row * 256 + ((unit ^ (row & 7)) << 4));
}

__global__ __launch_bounds__(256, 1) void attn_mma_kernel(
    const unsigned char* __restrict__ mask)
{
    extern __shared__ char sm8[];
    const uint32_t sb = smem_u32(sm8);

    const int bid = blockIdx.x;
    // LPT: qt-major descending, bh-minor.
    const int qt = NQT2 - 1 - (bid >> 5);
    const int bh = bid & 31;
    const int b = bh / NH;
    const int h = bh % NH;
    const int q0 = qt * ATQ2;
    const int NKT = 2 * qt + 2;               // 64-key tiles covering [0, q0+128)

    const int tid = threadIdx.x;
    const int lane = tid & 31;
    const int w = tid >> 5;                   // warp 0..7 -> rows w*16..w*16+15
    const int lq = lane >> 2;
    const int lr = lane & 3;
    const float inv_norm = 0.08838834764831845f;

    const __nv_bfloat16* KhB = g_kh + (size_t)bh * S_LEN * HD;
    const __nv_bfloat16* KlB = g_kl + (size_t)bh * S_LEN * HD;
    const __nv_bfloat16* VhB = g_vh + (size_t)bh * S_LEN * HD;
    const __nv_bfloat16* VlB = g_vl + (size_t)bh * S_LEN * HD;

    // per-thread cp.async geometry for one 64x128 bf16 tile (16KB)
    int cRow[4], cUn[4];
    uint32_t cSwz[4];
#pragma unroll
    for (int i = 0; i < 4; i++) {
        int u = tid + i * 256;
        cRow[i] = u >> 4;
        cUn[i]  = u & 15;
        cSwz[i] = soff(cRow[i], cUn[i]);
    }

    // issue KV stage 0 -> buf0
    {
        const uint32_t sp = sb;
#pragma unroll
        for (int i = 0; i < 4; i++) {
            const size_t g = (size_t)cRow[i] * HD + cUn[i] * 8;
            cp16(sp + KO_H + cSwz[i], KhB + g);
            cp16(sp + KO_L + cSwz[i], KlB + g);
            cp16(sp + VO_H + cSwz[i], VhB + g);
            cp16(sp + VO_L + cSwz[i], VlB + g);
        }
        CP_COMMIT();
    }

    // stage Q into buf2 (plain stores), then pull fragments into registers
    {
        const __nv_bfloat16* Qh = g_qh + ((size_t)bh * S_LEN + q0) * HD;
        const __nv_bfloat16* Ql = g_ql + ((size_t)bh * S_LEN + q0) * HD;
#pragma unroll
        for (int i = 0; i < 8; i++) {
            int u = tid + i * 256;
            int row = u >> 4, un = u & 15;
            uint32_t off = soff(row, un);
            *(uint4*)(sm8 + 2 * AT_STAGE + off) = ((const uint4*)(Qh + row * HD))[un];
            *(uint4*)(sm8 + 2 * AT_STAGE + 32768 + off) = ((const uint4*)(Ql + row * HD))[un];
        }
    }
    __syncthreads();

    uint32_t qfh[8][4], qfl[8][4];
    {
        const int r = w * 16 + (lane & 15);
#pragma unroll
        for (int ks = 0; ks < 8; ks++) {
            int un = ks * 2 + (lane >> 4);
            uint32_t off = soff(r, un);
            ldmx4(qfh[ks], sb + 2 * AT_STAGE + off);
            ldmx4(qfl[ks], sb + 2 * AT_STAGE + 32768 + off);
        }
    }

    // issue KV stage 1 -> buf1 (buf1 untouched so far; no extra barrier)
    if (1 < NKT) {
        const uint32_t sp = sb + AT_STAGE;
        const size_t kbase = (size_t)64 * HD;
#pragma unroll
        for (int i = 0; i < 4; i++) {
            const size_t g = kbase + (size_t)cRow[i] * HD + cUn[i] * 8;
            cp16(sp + KO_H + cSwz[i], KhB + g);
            cp16(sp + KO_L + cSwz[i], KlB + g);
            cp16(sp + VO_H + cSwz[i], VhB + g);
            cp16(sp + VO_L + cSwz[i], VlB + g);
        }
    }
    CP_COMMIT();

    const int sg0 = q0 + w * 16 + lq;
    const int sg1 = sg0 + 8;
    const int wRowMax = q0 + w * 16 + 15;
    const unsigned char* mrow0 = mask + ((size_t)b * S_LEN + sg0) * S_LEN;
    const unsigned char* mrow1 = mask + ((size_t)b * S_LEN + sg1) * S_LEN;

    float m0 = -1e30f, m1 = -1e30f, l0 = 0.0f, l1 = 0.0f;
    float o[16][4];
#pragma unroll
    for (int jd = 0; jd < 16; jd++)
#pragma unroll
        for (int e = 0; e < 4; e++) o[jd][e] = 0.0f;

    int buf = 0;
    for (int kt = 0; kt < NKT; ++kt) {
        CP_WAIT(1);
        __syncthreads();   // (a) kt's data visible; (b) compute kt-1 done by all
                           //     -> buffer (kt+2)%3 (read at kt-1) is free

        // issue loads for kt+2
        if (kt + 2 < NKT) {
            const uint32_t sp = sb + ((kt + 2) % 3) * AT_STAGE;
            const size_t kbase = (size_t)(kt + 2) * 64 * HD;
#pragma unroll
            for (int i = 0; i < 4; i++) {
                const size_t g = kbase + (size_t)cRow[i] * HD + cUn[i] * 8;
                cp16(sp + KO_H + cSwz[i], KhB + g);
                cp16(sp + KO_L + cSwz[i], KlB + g);
                cp16(sp + VO_H + cSwz[i], VhB + g);
                cp16(sp + VO_L + cSwz[i], VlB + g);
            }
        }
        CP_COMMIT();

        const int k0 = kt * 64;
        if (k0 <= wRowMax) {   // warp-uniform causal skip
            const uint32_t kb = sb + buf * AT_STAGE;

            float c[8][4];
#pragma unroll
            for (int j = 0; j < 8; j++)
#pragma unroll
                for (int e = 0; e < 4; e++) c[j][e] = 0.0f;

#pragma unroll
            for (int ks = 0; ks < 8; ks++) {
#pragma unroll
                for (int nt = 0; nt < 4; nt++) {
                    int r = nt * 16 + (lane & 7) + ((lane >> 4) & 1) * 8;
                    int un = ks * 2 + ((lane >> 3) & 1);
                    uint32_t off = soff(r, un);
                    uint32_t kh4[4], kl4[4];
                    ldmx4(kh4, kb + KO_H + off);
                    ldmx4(kl4, kb + KO_L + off);
                    mma_bf16(c[2 * nt], qfh[ks][0], qfh[ks][1], qfh[ks][2], qfh[ks][3],
                             kh4[0], kh4[1]);
                    mma_bf16(c[2 * nt], qfh[ks][0], qfh[ks][1], qfh[ks][2], qfh[ks][3],
                             kl4[0], kl4[1]);
                    mma_bf16(c[2 * nt], qfl[ks][0], qfl[ks][1], qfl[ks][2], qfl[ks][3],
                             kh4[0], kh4[1]);
                    mma_bf16(c[2 * nt + 1], qfh[ks][0], qfh[ks][1], qfh[ks][2], qfh[ks][3],
                             kh4[2], kh4[3]);
                    mma_bf16(c[2 * nt + 1], qfh[ks][0], qfh[ks][1], qfh[ks][2], qfh[ks][3],
                             kl4[2], kl4[3]);
                    mma_bf16(c[2 * nt + 1], qfl[ks][0], qfl[ks][1], qfl[ks][2], qfl[ks][3],
                             kh4[2], kh4[3]);
                }
            }

#pragma unroll
            for (int j = 0; j < 8; j++) {
                const int t0 = k0 + j * 8 + 2 * lr;
                uchar2 mb0 = *(const uchar2*)(mrow0 + t0);
                uchar2 mb1 = *(const uchar2*)(mrow1 + t0);
                c[j][0] = (t0 > sg0     || mb0.x) ? -10000.0f : c[j][0] * inv_norm;
                c[j][1] = (t0 + 1 > sg0 || mb0.y) ? -10000.0f : c[j][1] * inv_norm;
                c[j][2] = (t0 > sg1     || mb1.x) ? -10000.0f : c[j][2] * inv_norm;
                c[j][3] = (t0 + 1 > sg1 || mb1.y) ? -10000.0f : c[j][3] * inv_norm;
            }

            float vm0 = -1e30f, vm1 = -1e30f;
#pragma unroll
            for (int j = 0; j < 8; j++) {
                vm0 = fmaxf(vm0, fmaxf(c[j][0], c[j][1]));
                vm1 = fmaxf(vm1, fmaxf(c[j][2], c[j][3]));
            }
            vm0 = fmaxf(vm0, __shfl_xor_sync(0xffffffffu, vm0, 1));
            vm0 = fmaxf(vm0, __shfl_xor_sync(0xffffffffu, vm0, 2));
            vm1 = fmaxf(vm1, __shfl_xor_sync(0xffffffffu, vm1, 1));
            vm1 = fmaxf(vm1, __shfl_xor_sync(0xffffffffu, vm1, 2));
            const float mn0 = fmaxf(m0, vm0), mn1 = fmaxf(m1, vm1);
            const float cor0 = __expf(m0 - mn0), cor1 = __expf(m1 - mn1);
            m0 = mn0; m1 = mn1;

            uint32_t aPh[8][2], aPl[8][2];
            float ls0 = 0.0f, ls1 = 0.0f;
#pragma unroll
            for (int j = 0; j < 8; j++) {
                float p0 = __expf(c[j][0] - mn0);
                float p1 = __expf(c[j][1] - mn0);
                float p2 = __expf(c[j][2] - mn1);
                float p3 = __expf(c[j][3] - mn1);
                ls0 += p0 + p1; ls1 += p2 + p3;
                __nv_bfloat162 h01 = __floats2bfloat162_rn(p0, p1);
                __nv_bfloat162 h23 = __floats2bfloat162_rn(p2, p3);
                __nv_bfloat162 l01 = __floats2bfloat162_rn(
                    p0 - __bfloat162float(h01.x), p1 - __bfloat162float(h01.y));
                __nv_bfloat162 l23 = __floats2bfloat162_rn(
                    p2 - __bfloat162float(h23.x), p3 - __bfloat162float(h23.y));
                aPh[j][0] = *(uint32_t*)&h01;
                aPh[j][1] = *(uint32_t*)&h23;
                aPl[j][0] = *(uint32_t*)&l01;
                aPl[j][1] = *(uint32_t*)&l23;
            }
            l0 = l0 * cor0 + ls0;
            l1 = l1 * cor1 + ls1;
#pragma unroll
            for (int jd = 0; jd < 16; jd++) {
                o[jd][0] *= cor0; o[jd][1] *= cor0;
                o[jd][2] *= cor1; o[jd][3] *= cor1;
            }

#pragma unroll
            for (int ss = 0; ss < 4; ss++) {
                const uint32_t ah0 = aPh[2 * ss][0], ah1 = aPh[2 * ss][1];
                const uint32_t ah2 = aPh[2 * ss + 1][0], ah3 = aPh[2 * ss + 1][1];
                const uint32_t al0 = aPl[2 * ss][0], al1 = aPl[2 * ss][1];
                const uint32_t al2 = aPl[2 * ss + 1][0], al3 = aPl[2 * ss + 1][1];
                int r = ss * 16 + (lane & 7) + ((lane >> 3) & 1) * 8;
#pragma unroll
                for (int dt = 0; dt < 8; dt++) {
                    int un = dt * 2 + ((lane >> 4) & 1);
                    uint32_t off = soff(r, un);
                    uint32_t vh4[4], vl4[4];
                    ldmx4t(vh4, kb + VO_H + off);
                    ldmx4t(vl4, kb + VO_L + off);
                    mma_bf16(o[2 * dt], ah0, ah1, ah2, ah3, vh4[0], vh4[1]);
                    mma_bf16(o[2 * dt], ah0, ah1, ah2, ah3, vl4[0], vl4[1]);
                    mma_bf16(o[2 * dt], al0, al1, al2, al3, vh4[0], vh4[1]);
                    mma_bf16(o[2 * dt + 1], ah0, ah1, ah2, ah3, vh4[2], vh4[3]);
                    mma_bf16(o[2 * dt + 1], ah0, ah1, ah2, ah3, vl4[2], vl4[3]);
                    mma_bf16(o[2 * dt + 1], al0, al1, al2, al3, vh4[2], vh4[3]);
                }
            }
        }
        buf = (buf + 1 == 3) ? 0 : buf + 1;
    }

    l0 += __shfl_xor_sync(0xffffffffu, l0, 1);
    l0 += __shfl_xor_sync(0xffffffffu, l0, 2);
    l1 += __shfl_xor_sync(0xffffffffu, l1, 1);
    l1 += __shfl_xor_sync(0xffffffffu, l1, 2);
    const float inv0 = 1.0f / l0, inv1 = 1.0f / l1;

    __nv_bfloat16* chiBase = g_chi + (size_t)h * HD;
    __nv_bfloat16* cloBase = g_clo + (size_t)h * HD;
    const size_t row0 = (size_t)(sg0 * BATCH + b) * HID;
    const size_t row1 = (size_t)(sg1 * BATCH + b) * HID;
#pragma unroll
    for (int jd = 0; jd < 16; jd++) {
        const int d = jd * 8 + 2 * lr;
        float v0 = o[jd][0] * inv0, v1 = o[jd][1] * inv0;
        float v2 = o[jd][2] * inv1, v3 = o[jd][3] * inv1;
        __nv_bfloat162 h01 = __floats2bfloat162_rn(v0, v1);
        __nv_bfloat162 l01 = __floats2bfloat162_rn(
            v0 - __bfloat162float(h01.x), v1 - __bfloat162float(h01.y));
        __nv_bfloat162 h23 = __floats2bfloat162_rn(v2, v3);
        __nv_bfloat162 l23 = __floats2bfloat162_rn(
            v2 - __bfloat162float(h23.x), v3 - __bfloat162float(h23.y));
        *(__nv_bfloat162*)(chiBase + row0 + d) = h01;
        *(__nv_bfloat162*)(cloBase + row0 + d) = l01;
        *(__nv_bfloat162*)(chiBase + row1 + d) = h23;
        *(__nv_bfloat162*)(cloBase + row1 + d) = l23;
    }
}

__global__ void copy_bias_kernel(const float* __restrict__ bias, float* __restrict__ dst)
{
    int i = blockIdx.x * blockDim.x + threadIdx.x;
    if (i < HID) dst[i] = bias[i];
}

// ---------------------------------------------------------------------------
extern "C" void kernel_launch(void* const* d_in, const int* in_sizes, int n_in,
                              void* d_out, int out_size)
{
    const float* hidden   = (const float*)d_in[0];
    const unsigned char* mask = (const unsigned char*)d_in[1];
    const float* qkv_w    = (const float*)d_in[2];
    const float* qkv_b    = (const float*)d_in[3];
    const float* proj_w   = (const float*)d_in[4];
    const float* proj_b   = (const float*)d_in[5];
    float* out = (float*)d_out;

    cudaFuncSetAttribute(attn_mma_kernel,
                         cudaFuncAttributeMaxDynamicSharedMemorySize, A3_SMEM);
    cudaFuncSetAttribute(gemm_hmma_kernel<N3H, 0>,
                         cudaFuncAttributeMaxDynamicSharedMemorySize, GEMM_DSMEM);
    cudaFuncSetAttribute(gemm_hmma_kernel<HID, 1>,
                         cudaFuncAttributeMaxDynamicSharedMemorySize, GEMM_DSMEM);

    // 1. prep splits
    split_hidden_kernel<<<M_ROWS * HID / 256, 256>>>(hidden);
    transpose_split_kernel<N3H, 0><<<dim3(N3H / 32, HID / 32), dim3(32, 8)>>>(qkv_w);
    transpose_split_kernel<HID, 1><<<dim3(HID / 32, HID / 32), dim3(32, 8)>>>(proj_w);

    // 2. QKV GEMM -> bf16 hi/lo q/k/v (staged coalesced epilogue)
    gemm_hmma_kernel<N3H, 0><<<dim3(N3H / 128, M_ROWS / 128), 256, GEMM_DSMEM>>>(qkv_b, nullptr);

    // 3. MMA flash attention v3 (Q-in-regs, 3-stage KV, LPT) -> bf16 hi/lo ctx
    attn_mma_kernel<<<NBH * NQT2, 256, A3_SMEM>>>(mask);

    // 4. proj GEMM -> out
    gemm_hmma_kernel<HID, 1><<<dim3(HID / 128, M_ROWS / 128), 256, GEMM_DSMEM>>>(nullptr, out);

    if (out_size > M_ROWS * HID) {
        copy_bias_kernel<<<(HID + 255) / 256, 256>>>(proj_b, out + (size_t)M_ROWS * HID);
    }
}